// round 15
// baseline (speedup 1.0000x reference)
#include <cuda_runtime.h>
#include <cuda_bf16.h>
#include <math.h>
#include <stdint.h>

constexpr int CB  = 4;
constexpr int CN  = 4096;
constexpr int CD  = 512;
constexpr int CH  = 8;
constexpr int CDH = 64;
constexpr int CM  = 256;
constexpr int CL  = 16;
constexpr int CBH = CB * CH;    // 32
constexpr int CT3 = 3 * CD;     // 1536
constexpr float EPS = 1e-5f;

typedef __nv_bfloat16 bf16;
typedef __nv_bfloat162 bf162;

// ---------------------------------------------------------------------------
// Device scratch
// ---------------------------------------------------------------------------
__device__ __align__(16) bf16 g_xn  [(size_t)CB * CN * CD];
__device__ __align__(16) bf16 g_xl  [(size_t)CB * CM * CD];
__device__ __align__(16) bf16 g_q   [(size_t)CBH * CN * CDH];
__device__ __align__(16) bf16 g_v   [(size_t)CBH * CN * CDH];
__device__ __align__(16) bf16 g_kT  [(size_t)CBH * CDH * CN];
__device__ __align__(16) bf16 g_ql  [(size_t)CBH * CM * CDH];
__device__ __align__(16) bf16 g_klT [(size_t)CBH * CDH * CM];
__device__ __align__(16) bf16 g_a1  [(size_t)CBH * CN * CM];
__device__ __align__(16) bf16 g_a2  [(size_t)CBH * CM * CM];
__device__ __align__(16) bf16 g_z   [(size_t)CBH * CM * CM];
__device__ __align__(16) bf16 g_z2  [(size_t)CBH * CM * CM];
__device__ __align__(16) bf16 g_xz  [(size_t)CBH * CM * CM];
__device__ __align__(16) bf16 g_t   [(size_t)CBH * CM * CM];
__device__ __align__(16) bf16 g_u   [(size_t)CBH * CM * CM];
__device__ __align__(16) bf16 g_av  [(size_t)CBH * CM * CDH];
__device__ __align__(16) bf16 g_zav [(size_t)CBH * CM * CDH];
__device__ __align__(16) bf16 g_outh[(size_t)CBH * CN * CDH];
__device__ __align__(16) bf16 g_wq16[(size_t)CD * CT3];
__device__ __align__(16) bf16 g_wo16[(size_t)CD * CD];
__device__ unsigned g_maxc, g_maxr;

// ---------------------------------------------------------------------------
// Fork/join resources (host-side only; created once at static init)
// ---------------------------------------------------------------------------
struct AuxStreams {
    cudaStream_t s1, s2;
    cudaEvent_t evF, evZ, evAV, evJ, evJ2, evO2;
    AuxStreams() {
        cudaStreamCreateWithFlags(&s1, cudaStreamNonBlocking);
        cudaStreamCreateWithFlags(&s2, cudaStreamNonBlocking);
        cudaEventCreateWithFlags(&evF,  cudaEventDisableTiming);
        cudaEventCreateWithFlags(&evZ,  cudaEventDisableTiming);
        cudaEventCreateWithFlags(&evAV, cudaEventDisableTiming);
        cudaEventCreateWithFlags(&evJ,  cudaEventDisableTiming);
        cudaEventCreateWithFlags(&evJ2, cudaEventDisableTiming);
        cudaEventCreateWithFlags(&evO2, cudaEventDisableTiming);
    }
};
static AuxStreams g_aux;

// ---------------------------------------------------------------------------
// helpers
// ---------------------------------------------------------------------------
__device__ __forceinline__ uint32_t pack2(float a, float b) {
    bf162 h = __floats2bfloat162_rn(a, b);
    return *reinterpret_cast<uint32_t*>(&h);
}
__device__ __forceinline__ float2 unpk(uint32_t u) {
    bf162 h = *reinterpret_cast<bf162*>(&u);
    return __bfloat1622float2(h);
}
__device__ __forceinline__ void mma16(float* c, const uint32_t* a,
                                      uint32_t b0, uint32_t b1) {
    asm volatile(
        "mma.sync.aligned.m16n8k16.row.col.f32.bf16.bf16.f32 "
        "{%0,%1,%2,%3},{%4,%5,%6,%7},{%8,%9},{%0,%1,%2,%3};"
        : "+f"(c[0]), "+f"(c[1]), "+f"(c[2]), "+f"(c[3])
        : "r"(a[0]), "r"(a[1]), "r"(a[2]), "r"(a[3]), "r"(b0), "r"(b1));
}
__device__ __forceinline__ void ldsm4(uint32_t* r, uint32_t addr) {
    asm volatile(
        "ldmatrix.sync.aligned.m8n8.x4.shared.b16 {%0,%1,%2,%3},[%4];"
        : "=r"(r[0]), "=r"(r[1]), "=r"(r[2]), "=r"(r[3]) : "r"(addr));
}
__device__ __forceinline__ void ldsm4t(uint32_t& r0, uint32_t& r1,
                                       uint32_t& r2, uint32_t& r3, uint32_t addr) {
    asm volatile(
        "ldmatrix.sync.aligned.m8n8.x4.trans.shared.b16 {%0,%1,%2,%3},[%4];"
        : "=r"(r0), "=r"(r1), "=r"(r2), "=r"(r3) : "r"(addr));
}

// ---------------------------------------------------------------------------
// bf16 tensor-core batched GEMM.  C = alpha * A @ (diagc*I + bsign*B)
// MODE 0: bf16 store  1: QKV scatter  2: final fp32 (+X+bias, gather A)
// MODE 3: fused row softmax (BN == row width)  4: bf16 accumulate
// MODE 5: landmark scatter (rows=B*CM; q-cols -> g_ql*0.125, k-cols -> g_klT)
// xoff: column-block offset.  yoff: row-block offset.
// ysplit >= 0: row-block mapping by = (y/16)*32 + (y%16) + ysplit*16
// ---------------------------------------------------------------------------
template <int BM, int BN, int WGM, int WGN, int MODE, bool DIAG, int MINB>
__global__ __launch_bounds__(256, MINB)
void tc_gemm(const bf16* __restrict__ A, const bf16* __restrict__ B,
             void* __restrict__ Cp,
             int K, int lda, int ldb, int ldc,
             size_t sA, size_t sB, size_t sC,
             float alpha, float diagc, float bsign,
             const float* __restrict__ X, const float* __restrict__ bias,
             int xoff, int yoff, int ysplit) {
    constexpr int WROWS = BM / WGM;
    constexpr int WCOLS = BN / WGN;
    constexpr int MI    = WROWS / 16;
    constexpr int NFR   = WCOLS / 8;
    constexpr int TPRA  = 256 / BM;
    constexpr int KSPAN = 32 / TPRA;
    constexpr int NU4   = KSPAN / 8;
    constexpr int TPRB  = BN / 8;
    constexpr int RPPB  = 256 / TPRB;
    constexpr int BPASS = 32 / RPPB;
    constexpr int AP    = 40;
    constexpr int BPH   = BN + 8;

    __shared__ bf16 As[BM * AP];
    __shared__ bf16 Bs[32 * BPH];
    __shared__ float sred[(MODE == 3) ? 2 * BM * WGN : 2];

    const int t = threadIdx.x, warp = t >> 5, lane = t & 31;
    const int wm = warp / WGN, wn = warp % WGN;
    const int g = lane >> 2, tg = lane & 3;
    int by = blockIdx.y + yoff;
    if (ysplit >= 0)
        by = ((blockIdx.y >> 4) << 5) + (blockIdx.y & 15) + ysplit * 16;
    const int rowBase = by * BM;
    const int colBase = (blockIdx.x + xoff) * BN;
    const int arow = t % BM, akg = (t / BM) * KSPAN;
    const int brow = t / TPRB, bcol = (t % TPRB) * 8;

    const bf16* Ab = A + blockIdx.z * sA;
    const bf16* Bb = B + blockIdx.z * sB;

    const uint32_t asb = (uint32_t)__cvta_generic_to_shared(As);
    const uint32_t bsb = (uint32_t)__cvta_generic_to_shared(Bs);
    const uint32_t aoff = asb +
        ((((lane >> 3) & 1) * 8 + (lane & 7)) * AP + (lane >> 4) * 8) * 2;
    const uint32_t boff = bsb +
        ((((lane >> 3) & 1) * 8 + (lane & 7)) * BPH + wn * WCOLS + (lane >> 4) * 8) * 2;

    uint4 pa[NU4];
    uint4 pbb[BPASS];

    auto ldA = [&](int k0) {
        if (MODE == 2) {
            int r = rowBase + arow;
            int b_ = r >> 12, n = r & (CN - 1);
            int c = k0 + akg;
            int h_ = c >> 6, dh = c & 63;
            const bf16* p = Ab + ((((size_t)(b_ * CH + h_)) * CN + n) * CDH + dh);
#pragma unroll
            for (int i = 0; i < NU4; i++) pa[i] = *(const uint4*)(p + i * 8);
        } else {
            const bf16* p = Ab + (size_t)(rowBase + arow) * lda + k0 + akg;
#pragma unroll
            for (int i = 0; i < NU4; i++) pa[i] = *(const uint4*)(p + i * 8);
        }
    };
    auto ldB = [&](int k0) {
#pragma unroll
        for (int i = 0; i < BPASS; i++)
            pbb[i] = *(const uint4*)(Bb + (size_t)(k0 + brow + i * RPPB) * ldb +
                                     colBase + bcol);
    };
    auto stage = [&](int k0) {
#pragma unroll
        for (int i = 0; i < NU4; i++)
            *(uint4*)&As[arow * AP + akg + i * 8] = pa[i];
#pragma unroll
        for (int i = 0; i < BPASS; i++) {
            int r = brow + i * RPPB;
            uint4 u;
            if (DIAG) {
                float e[8];
                float2 f;
                f = unpk(pbb[i].x); e[0] = f.x; e[1] = f.y;
                f = unpk(pbb[i].y); e[2] = f.x; e[3] = f.y;
                f = unpk(pbb[i].z); e[4] = f.x; e[5] = f.y;
                f = unpk(pbb[i].w); e[6] = f.x; e[7] = f.y;
                int kr = k0 + r;
                int cb = colBase + bcol;
#pragma unroll
                for (int j = 0; j < 8; j++)
                    e[j] = bsign * e[j] + ((kr == cb + j) ? diagc : 0.0f);
                u.x = pack2(e[0], e[1]); u.y = pack2(e[2], e[3]);
                u.z = pack2(e[4], e[5]); u.w = pack2(e[6], e[7]);
            } else {
                u = pbb[i];
            }
            *(uint4*)&Bs[r * BPH + bcol] = u;
        }
    };

    float acc[MI][NFR][4] = {};

    ldA(0); ldB(0); stage(0);
    __syncthreads();
    for (int k0 = 0;; k0 += 32) {
        const int kn = k0 + 32;
        const bool more = kn < K;
        if (more) { ldA(kn); ldB(kn); }
#pragma unroll
        for (int ks = 0; ks < 2; ks++) {
            uint32_t af[MI][4];
#pragma unroll
            for (int mi = 0; mi < MI; mi++)
                ldsm4(af[mi], aoff + ((wm * WROWS + mi * 16) * AP + ks * 16) * 2);
            uint32_t bfr[NFR][2];
#pragma unroll
            for (int np = 0; np < NFR / 2; np++)
                ldsm4t(bfr[2 * np][0], bfr[2 * np][1],
                       bfr[2 * np + 1][0], bfr[2 * np + 1][1],
                       boff + (ks * 16 * BPH + np * 16) * 2);
#pragma unroll
            for (int ni = 0; ni < NFR; ni++)
#pragma unroll
                for (int mi = 0; mi < MI; mi++)
                    mma16(acc[mi][ni], af[mi], bfr[ni][0], bfr[ni][1]);
        }
        if (!more) break;
        __syncthreads();
        stage(kn);
        __syncthreads();
    }

    bf16*  Cb16 = (bf16*)Cp + blockIdx.z * sC;
    float* Cbf  = (float*)Cp + blockIdx.z * sC;

    if (MODE == 3) {
        float* smax = sred;
        float* ssum = sred + BM * WGN;
#pragma unroll
        for (int mi = 0; mi < MI; mi++)
#pragma unroll
            for (int h2 = 0; h2 < 2; h2++) {
                float m = -3.4e38f;
#pragma unroll
                for (int ni = 0; ni < NFR; ni++) {
                    m = fmaxf(m, acc[mi][ni][h2 * 2]);
                    m = fmaxf(m, acc[mi][ni][h2 * 2 + 1]);
                }
                m = fmaxf(m, __shfl_xor_sync(0xffffffffu, m, 1));
                m = fmaxf(m, __shfl_xor_sync(0xffffffffu, m, 2));
                int rl = wm * WROWS + mi * 16 + h2 * 8 + g;
                if (tg == 0) smax[rl * WGN + wn] = m;
            }
        __syncthreads();
#pragma unroll
        for (int mi = 0; mi < MI; mi++)
#pragma unroll
            for (int h2 = 0; h2 < 2; h2++) {
                int rl = wm * WROWS + mi * 16 + h2 * 8 + g;
                float tm = smax[rl * WGN];
#pragma unroll
                for (int w = 1; w < WGN; w++) tm = fmaxf(tm, smax[rl * WGN + w]);
                float s = 0.0f;
#pragma unroll
                for (int ni = 0; ni < NFR; ni++) {
                    float e0 = __expf(acc[mi][ni][h2 * 2]     - tm);
                    float e1 = __expf(acc[mi][ni][h2 * 2 + 1] - tm);
                    acc[mi][ni][h2 * 2]     = e0;
                    acc[mi][ni][h2 * 2 + 1] = e1;
                    s += e0 + e1;
                }
                s += __shfl_xor_sync(0xffffffffu, s, 1);
                s += __shfl_xor_sync(0xffffffffu, s, 2);
                if (tg == 0) ssum[rl * WGN + wn] = s;
            }
        __syncthreads();
#pragma unroll
        for (int mi = 0; mi < MI; mi++)
#pragma unroll
            for (int h2 = 0; h2 < 2; h2++) {
                int rl = wm * WROWS + mi * 16 + h2 * 8 + g;
                float s = 0.0f;
#pragma unroll
                for (int w = 0; w < WGN; w++) s += ssum[rl * WGN + w];
                float inv = 1.0f / s;
                int r = rowBase + rl;
#pragma unroll
                for (int ni = 0; ni < NFR; ni++) {
                    int c0 = colBase + wn * WCOLS + ni * 8 + 2 * tg;
                    *(uint32_t*)&Cb16[(size_t)r * ldc + c0] =
                        pack2(acc[mi][ni][h2 * 2] * inv,
                              acc[mi][ni][h2 * 2 + 1] * inv);
                }
            }
        return;
    }

#pragma unroll
    for (int mi = 0; mi < MI; mi++)
#pragma unroll
        for (int ni = 0; ni < NFR; ni++) {
            int r0 = rowBase + wm * WROWS + mi * 16 + g;
            int c0 = colBase + wn * WCOLS + ni * 8 + 2 * tg;
#pragma unroll
            for (int h2 = 0; h2 < 2; h2++) {
                int r = r0 + h2 * 8;
                float vx = alpha * acc[mi][ni][h2 * 2];
                float vy = alpha * acc[mi][ni][h2 * 2 + 1];
                if (MODE == 0) {
                    *(uint32_t*)&Cb16[(size_t)r * ldc + c0] = pack2(vx, vy);
                } else if (MODE == 4) {
                    uint32_t old = *(uint32_t*)&Cb16[(size_t)r * ldc + c0];
                    float2 f = unpk(old);
                    *(uint32_t*)&Cb16[(size_t)r * ldc + c0] =
                        pack2(vx + f.x, vy + f.y);
                } else if (MODE == 1) {
                    int b_ = r >> 12, n = r & (CN - 1);
                    int which = c0 >> 9, inner = c0 & 511;
                    int h_ = inner >> 6, dh = inner & 63;
                    size_t off = (((size_t)(b_ * CH + h_)) * CN + n) * CDH + dh;
                    if (which == 0) {
                        *(uint32_t*)&g_q[off] = pack2(vx * 0.125f, vy * 0.125f);
                    } else if (which == 1) {
                        size_t ot = (((size_t)(b_ * CH + h_)) * CDH + dh) * CN + n;
                        g_kT[ot]      = __float2bfloat16(vx);
                        g_kT[ot + CN] = __float2bfloat16(vy);
                    } else {
                        *(uint32_t*)&g_v[off] = pack2(vx, vy);
                    }
                } else if (MODE == 5) {
                    int b_ = r >> 8, mi2 = r & (CM - 1);
                    int which = c0 >> 9, inner = c0 & 511;
                    int h_ = inner >> 6, dh = inner & 63;
                    if (which == 0) {
                        size_t off = (((size_t)(b_ * CH + h_)) * CM + mi2) * CDH + dh;
                        *(uint32_t*)&g_ql[off] = pack2(vx * 0.125f, vy * 0.125f);
                    } else {
                        size_t ot = (((size_t)(b_ * CH + h_)) * CDH + dh) * CM + mi2;
                        g_klT[ot]      = __float2bfloat16(vx);
                        g_klT[ot + CM] = __float2bfloat16(vy);
                    }
                } else {
                    size_t o = (size_t)r * CD + c0;
                    float2 xr = *(const float2*)&X[o];
                    float2 br = *(const float2*)&bias[c0];
                    *(float2*)&Cbf[o] = make_float2(vx + xr.x + br.x,
                                                    vy + xr.y + br.y);
                }
            }
        }
}

// ---------------------------------------------------------------------------
// Flash kernel: av = softmax_rows(ql @ k^T) @ v   (per bh, 128 m-rows/CTA)
// ---------------------------------------------------------------------------
__global__ __launch_bounds__(256, 1)
void flash_av() {
    constexpr int KP = 136;
    constexpr int VP = 72;
    __shared__ bf16 Ks[64 * KP];
    __shared__ bf16 Vs[128 * VP];

    const int t = threadIdx.x, warp = t >> 5, lane = t & 31;
    const int g = lane >> 2, tg = lane & 3;
    const int mb = blockIdx.x, bh = blockIdx.y;

    const bf16* qlb = g_ql + ((size_t)bh * CM + mb * 128) * CDH;
    const bf16* kTb = g_kT + (size_t)bh * CDH * CN;
    const bf16* vb  = g_v  + (size_t)bh * CN * CDH;

    const uint32_t ksb = (uint32_t)__cvta_generic_to_shared(Ks);
    const uint32_t vsb = (uint32_t)__cvta_generic_to_shared(Vs);
    const int rsel = ((lane >> 3) & 1) * 8 + (lane & 7);
    const int csel = (lane >> 4) * 8;

    for (int i = t; i < 1024; i += 256) {
        int row = i >> 3, cg = i & 7;
        *(uint4*)&Vs[row * VP + cg * 8] = *(const uint4*)&qlb[row * CDH + cg * 8];
    }
    __syncthreads();
    uint32_t qlA[4][4];
    {
        uint32_t base = vsb + ((warp * 16 + rsel) * VP + csel) * 2;
#pragma unroll
        for (int kb = 0; kb < 4; kb++) ldsm4(qlA[kb], base + kb * 16 * 2);
    }
    __syncthreads();

    float oacc[8][4] = {};
    float m0 = -1e30f, m1 = -1e30f, l0 = 0.0f, l1 = 0.0f;

    for (int ch = 0; ch < CN / 128; ch++) {
        for (int i = t; i < 1024; i += 256) {
            int row = i >> 4, cg = i & 15;
            *(uint4*)&Ks[row * KP + cg * 8] =
                *(const uint4*)&kTb[(size_t)row * CN + ch * 128 + cg * 8];
        }
        for (int i = t; i < 1024; i += 256) {
            int row = i >> 3, cg = i & 7;
            *(uint4*)&Vs[row * VP + cg * 8] =
                *(const uint4*)&vb[(size_t)(ch * 128 + row) * CDH + cg * 8];
        }
        __syncthreads();

        float sacc[16][4] = {};
#pragma unroll
        for (int ks = 0; ks < 4; ks++) {
            uint32_t brow = ksb + ((ks * 16 + rsel) * KP + csel) * 2;
#pragma unroll
            for (int np = 0; np < 8; np++) {
                uint32_t b0, b1, b2, b3;
                ldsm4t(b0, b1, b2, b3, brow + np * 16 * 2);
                mma16(sacc[2 * np],     qlA[ks], b0, b1);
                mma16(sacc[2 * np + 1], qlA[ks], b2, b3);
            }
        }

        float mx0 = m0, mx1 = m1;
#pragma unroll
        for (int ni = 0; ni < 16; ni++) {
            mx0 = fmaxf(mx0, fmaxf(sacc[ni][0], sacc[ni][1]));
            mx1 = fmaxf(mx1, fmaxf(sacc[ni][2], sacc[ni][3]));
        }
        mx0 = fmaxf(mx0, __shfl_xor_sync(0xffffffffu, mx0, 1));
        mx0 = fmaxf(mx0, __shfl_xor_sync(0xffffffffu, mx0, 2));
        mx1 = fmaxf(mx1, __shfl_xor_sync(0xffffffffu, mx1, 1));
        mx1 = fmaxf(mx1, __shfl_xor_sync(0xffffffffu, mx1, 2));
        float r0 = __expf(m0 - mx0), r1 = __expf(m1 - mx1);
        m0 = mx0; m1 = mx1;
        float s0 = 0.0f, s1 = 0.0f;
#pragma unroll
        for (int ni = 0; ni < 16; ni++) {
            sacc[ni][0] = __expf(sacc[ni][0] - m0);
            sacc[ni][1] = __expf(sacc[ni][1] - m0);
            sacc[ni][2] = __expf(sacc[ni][2] - m1);
            sacc[ni][3] = __expf(sacc[ni][3] - m1);
            s0 += sacc[ni][0] + sacc[ni][1];
            s1 += sacc[ni][2] + sacc[ni][3];
        }
        s0 += __shfl_xor_sync(0xffffffffu, s0, 1);
        s0 += __shfl_xor_sync(0xffffffffu, s0, 2);
        s1 += __shfl_xor_sync(0xffffffffu, s1, 1);
        s1 += __shfl_xor_sync(0xffffffffu, s1, 2);
        l0 = l0 * r0 + s0;
        l1 = l1 * r1 + s1;
#pragma unroll
        for (int f = 0; f < 8; f++) {
            oacc[f][0] *= r0; oacc[f][1] *= r0;
            oacc[f][2] *= r1; oacc[f][3] *= r1;
        }

#pragma unroll
        for (int kb = 0; kb < 8; kb++) {
            uint32_t pA[4];
            pA[0] = pack2(sacc[2 * kb][0],     sacc[2 * kb][1]);
            pA[1] = pack2(sacc[2 * kb][2],     sacc[2 * kb][3]);
            pA[2] = pack2(sacc[2 * kb + 1][0], sacc[2 * kb + 1][1]);
            pA[3] = pack2(sacc[2 * kb + 1][2], sacc[2 * kb + 1][3]);
            uint32_t vrow = vsb + ((kb * 16 + rsel) * VP + csel) * 2;
#pragma unroll
            for (int np = 0; np < 4; np++) {
                uint32_t b0, b1, b2, b3;
                ldsm4t(b0, b1, b2, b3, vrow + np * 16 * 2);
                mma16(oacc[2 * np],     pA, b0, b1);
                mma16(oacc[2 * np + 1], pA, b2, b3);
            }
        }
        __syncthreads();
    }

    float inv0 = 1.0f / l0, inv1 = 1.0f / l1;
    int row0 = mb * 128 + warp * 16 + g;
    bf16* avb = g_av + ((size_t)bh * CM) * CDH;
#pragma unroll
    for (int f = 0; f < 8; f++) {
        int c0 = f * 8 + 2 * tg;
        *(uint32_t*)&avb[(size_t)row0 * CDH + c0] =
            pack2(oacc[f][0] * inv0, oacc[f][1] * inv0);
        *(uint32_t*)&avb[(size_t)(row0 + 8) * CDH + c0] =
            pack2(oacc[f][2] * inv1, oacc[f][3] * inv1);
    }
}

// ---------------------------------------------------------------------------
__global__ void convert_w(const float* __restrict__ Wqkv,
                          const float* __restrict__ Wout) {
    int i = (blockIdx.x * 256 + threadIdx.x) * 4;
    const int n1 = CD * CT3;
    if (i < n1) {
        float4 v = *(const float4*)&Wqkv[i];
        uint2 o; o.x = pack2(v.x, v.y); o.y = pack2(v.z, v.w);
        *(uint2*)&g_wq16[i] = o;
    }
    if (i < CD * CD) {
        float4 v = *(const float4*)&Wout[i];
        uint2 o; o.x = pack2(v.x, v.y); o.y = pack2(v.z, v.w);
        *(uint2*)&g_wo16[i] = o;
    }
}

__global__ void ln_kernel(const float* __restrict__ x,
                          const float* __restrict__ gamma,
                          const float* __restrict__ beta) {
    int row = blockIdx.x;
    int t = threadIdx.x;
    const float4* xr = (const float4*)(x + (size_t)row * CD);
    float4 v = xr[t];
    float s  = v.x + v.y + v.z + v.w;
    float ss = v.x * v.x + v.y * v.y + v.z * v.z + v.w * v.w;
    __shared__ float shs[4], shss[4];
#pragma unroll
    for (int o = 16; o > 0; o >>= 1) {
        s  += __shfl_down_sync(0xffffffffu, s,  o);
        ss += __shfl_down_sync(0xffffffffu, ss, o);
    }
    int wid = t >> 5, lane = t & 31;
    if (!lane) { shs[wid] = s; shss[wid] = ss; }
    __syncthreads();
    s  = shs[0]  + shs[1]  + shs[2]  + shs[3];
    ss = shss[0] + shss[1] + shss[2] + shss[3];
    float mean = s * (1.0f / CD);
    float var  = ss * (1.0f / CD) - mean * mean;
    float inv  = rsqrtf(var + EPS);
    float4 gg = ((const float4*)gamma)[t];
    float4 bb = ((const float4*)beta)[t];
    uint2 o;
    o.x = pack2((v.x - mean) * inv * gg.x + bb.x, (v.y - mean) * inv * gg.y + bb.y);
    o.y = pack2((v.z - mean) * inv * gg.z + bb.z, (v.w - mean) * inv * gg.w + bb.w);
    *(uint2*)&g_xn[(size_t)row * CD + t * 4] = o;
}

// ---------------------------------------------------------------------------
// Group means of xn: xl[b*CM + m][c] = mean over 16 tokens of xn
// ---------------------------------------------------------------------------
__global__ void xlmean_kernel() {
    int idx = blockIdx.x * 256 + threadIdx.x;   // 1024 rows x 64 col-groups
    int cg = idx & 63;
    int row = idx >> 6;
    int b_ = row >> 8, mi = row & (CM - 1);
    size_t base = ((size_t)(b_ * CN + mi * CL)) * CD + cg * 8;
    float acc[8] = {};
    for (int j = 0; j < CL; j++) {
        uint4 u = *(const uint4*)&g_xn[base + (size_t)j * CD];
        const uint32_t* w = (const uint32_t*)&u;
#pragma unroll
        for (int e = 0; e < 4; e++) {
            float2 f = unpk(w[e]);
            acc[2 * e] += f.x; acc[2 * e + 1] += f.y;
        }
    }
    uint4 o;
    uint32_t* po = (uint32_t*)&o;
#pragma unroll
    for (int e = 0; e < 4; e++)
        po[e] = pack2(acc[2 * e] * (1.0f / CL), acc[2 * e + 1] * (1.0f / CL));
    *(uint4*)&g_xl[(size_t)row * CD + cg * 8] = o;
}

__global__ void init_scalars() { g_maxc = 0u; g_maxr = 0u; }

__global__ void absmax_sums() {
    int bh = blockIdx.x;
    int t = threadIdx.x;
    const bf16* a = g_a2 + (size_t)bh * CM * CM;
    float rs = 0.0f, cs = 0.0f;
    for (int j = 0; j < CM; j++) rs += fabsf(__bfloat162float(a[(size_t)t * CM + j]));
    for (int i = 0; i < CM; i++) cs += fabsf(__bfloat162float(a[(size_t)i * CM + t]));
    atomicMax(&g_maxc, __float_as_uint(rs));
    atomicMax(&g_maxr, __float_as_uint(cs));
}

__global__ void zinit_kernel() {
    int idx = blockIdx.x * 256 + threadIdx.x;
    int j = idx & 255;
    int i = (idx >> 8) & 255;
    int bh = idx >> 16;
    float denom = __uint_as_float(g_maxc) * __uint_as_float(g_maxr);
    g_z[((size_t)bh << 16) + (size_t)i * CM + j] =
        __float2bfloat16(__bfloat162float(g_a2[((size_t)bh << 16) + (size_t)j * CM + i]) / denom);
}

__global__ void conv_res(const float* __restrict__ w) {
    __shared__ float ws[33];
    int idx = blockIdx.x * 256 + threadIdx.x;
    int dh = idx & 63;
    int nq = (idx >> 6) & 1023;
    int bh = idx >> 16;
    int h_ = bh & 7;
    if (threadIdx.x < 33) ws[threadIdx.x] = w[h_ * 33 + threadIdx.x];
    __syncthreads();
    int n0 = nq * 4;
    size_t base = ((size_t)bh * CN) * CDH + dh;
    float vv[36];
#pragma unroll
    for (int j = 0; j < 36; j++) {
        int nn = n0 - 16 + j;
        vv[j] = (nn >= 0 && nn < CN)
                    ? __bfloat162float(g_v[base + (size_t)nn * CDH]) : 0.0f;
    }
#pragma unroll
    for (int i = 0; i < 4; i++) {
        float s = 0.0f;
#pragma unroll
        for (int k2 = 0; k2 < 33; k2++) s += ws[k2] * vv[k2 + i];
        g_outh[base + (size_t)(n0 + i) * CDH] = __float2bfloat16(s);
    }
}

// ---------------------------------------------------------------------------
// Launch (landmark-commute: prefix = LN -> xl -> ql/kl; QKV in window)
// ---------------------------------------------------------------------------
extern "C" void kernel_launch(void* const* d_in, const int* in_sizes, int n_in,
                              void* d_out, int out_size) {
    const float* x     = (const float*)d_in[0];
    const float* gamma = (const float*)d_in[1];
    const float* beta  = (const float*)d_in[2];
    const float* Wqkv  = (const float*)d_in[3];
    const float* Wout  = (const float*)d_in[4];
    const float* bout  = (const float*)d_in[5];
    const float* convw = (const float*)d_in[6];
    float* out = (float*)d_out;

    bf16 *xn, *xl, *q, *v, *kT, *ql, *klT, *a1, *a2;
    bf16 *z, *z2, *xz, *tb, *ub, *av, *zav, *outh, *wq16, *wo16;
    void* p;
    cudaGetSymbolAddress(&p, g_xn);   xn   = (bf16*)p;
    cudaGetSymbolAddress(&p, g_xl);   xl   = (bf16*)p;
    cudaGetSymbolAddress(&p, g_q);    q    = (bf16*)p;
    cudaGetSymbolAddress(&p, g_v);    v    = (bf16*)p;
    cudaGetSymbolAddress(&p, g_kT);   kT   = (bf16*)p;
    cudaGetSymbolAddress(&p, g_ql);   ql   = (bf16*)p;
    cudaGetSymbolAddress(&p, g_klT);  klT  = (bf16*)p;
    cudaGetSymbolAddress(&p, g_a1);   a1   = (bf16*)p;
    cudaGetSymbolAddress(&p, g_a2);   a2   = (bf16*)p;
    cudaGetSymbolAddress(&p, g_z);    z    = (bf16*)p;
    cudaGetSymbolAddress(&p, g_z2);   z2   = (bf16*)p;
    cudaGetSymbolAddress(&p, g_xz);   xz   = (bf16*)p;
    cudaGetSymbolAddress(&p, g_t);    tb   = (bf16*)p;
    cudaGetSymbolAddress(&p, g_u);    ub   = (bf16*)p;
    cudaGetSymbolAddress(&p, g_av);   av   = (bf16*)p;
    cudaGetSymbolAddress(&p, g_zav);  zav  = (bf16*)p;
    cudaGetSymbolAddress(&p, g_outh); outh = (bf16*)p;
    cudaGetSymbolAddress(&p, g_wq16); wq16 = (bf16*)p;
    cudaGetSymbolAddress(&p, g_wo16); wo16 = (bf16*)p;

    const size_t MM  = (size_t)CM * CM;
    const size_t NDH = (size_t)CN * CDH;
    const size_t AVH = (size_t)16 * CM * CDH;
    cudaStream_t s1 = g_aux.s1, s2 = g_aux.s2;
    const size_t HO = (size_t)16 * MM;

    // --- s0 prefix: LN, weights, group means, ql/kl projection ---
    ln_kernel<<<CB * CN, 128>>>(x, gamma, beta);
    convert_w<<<(CD * CT3) / 1024, 256>>>(Wqkv, Wout);
    xlmean_kernel<<<(CB * CM * CD / 8) / 256, 256>>>();
    tc_gemm<128, 256, 2, 4, 5, false, 1><<<dim3(4, CB * CM / 128, 1), 256>>>(
        xl, wq16, nullptr, CD, CD, CT3, 0, 0, 0, 0,
        1.0f, 0.0f, 1.0f, nullptr, nullptr, 0, 0, -1);
    cudaEventRecord(g_aux.evF, 0);

    // --- s1: a2 + pinv init + half-chain bh 0-15 (critical path) ---
    cudaStreamWaitEvent(s1, g_aux.evF, 0);
    tc_gemm<128, 256, 2, 4, 3, false, 1><<<dim3(1, CM / 128, CBH), 256, 0, s1>>>(
        ql, klT, a2, CDH, CDH, CM, CM,
        (size_t)CM * CDH, (size_t)CDH * CM, MM, 1.0f, 0.0f, 1.0f,
        nullptr, nullptr, 0, 0, -1);
    init_scalars<<<1, 1, 0, s1>>>();
    absmax_sums<<<CBH, 256, 0, s1>>>();
    zinit_kernel<<<(CBH * CM * CM) / 256, 256, 0, s1>>>();
    cudaEventRecord(g_aux.evZ, s1);
    cudaStreamWaitEvent(s2, g_aux.evZ, 0);

    bf16* zc = z;
    bf16* zn = z2;
    for (int it = 0; it < 5; it++) {
        tc_gemm<128, 256, 2, 4, 0, false, 1><<<dim3(1, 2, 16), 256, 0, s1>>>(
            a2, zc, xz, CM, CM, CM, CM, MM, MM, MM, 1.0f, 0.0f, 1.0f,
            nullptr, nullptr, 0, 0, -1);
        tc_gemm<128, 256, 2, 4, 0, true, 1><<<dim3(1, 2, 16), 256, 0, s1>>>(
            xz, xz, tb, CM, CM, CM, CM, MM, MM, MM, 1.0f, 7.0f, -1.0f,
            nullptr, nullptr, 0, 0, -1);
        tc_gemm<128, 256, 2, 4, 0, true, 1><<<dim3(1, 2, 16), 256, 0, s1>>>(
            xz, tb, ub, CM, CM, CM, CM, MM, MM, MM, 1.0f, 15.0f, -1.0f,
            nullptr, nullptr, 0, 0, -1);
        tc_gemm<128, 256, 2, 4, 0, true, 1><<<dim3(1, 2, 16), 256, 0, s1>>>(
            zc, ub, zn, CM, CM, CM, CM, MM, MM, MM, 0.25f, 13.0f, -1.0f,
            nullptr, nullptr, 0, 0, -1);
        tc_gemm<128, 256, 2, 4, 0, false, 1><<<dim3(1, 2, 16), 256, 0, s2>>>(
            a2 + HO, zc + HO, xz + HO, CM, CM, CM, CM, MM, MM, MM,
            1.0f, 0.0f, 1.0f, nullptr, nullptr, 0, 0, -1);
        tc_gemm<128, 256, 2, 4, 0, true, 1><<<dim3(1, 2, 16), 256, 0, s2>>>(
            xz + HO, xz + HO, tb + HO, CM, CM, CM, CM, MM, MM, MM,
            1.0f, 7.0f, -1.0f, nullptr, nullptr, 0, 0, -1);
        tc_gemm<128, 256, 2, 4, 0, true, 1><<<dim3(1, 2, 16), 256, 0, s2>>>(
            xz + HO, tb + HO, ub + HO, CM, CM, CM, CM, MM, MM, MM,
            1.0f, 15.0f, -1.0f, nullptr, nullptr, 0, 0, -1);
        tc_gemm<128, 256, 2, 4, 0, true, 1><<<dim3(1, 2, 16), 256, 0, s2>>>(
            zc + HO, ub + HO, zn + HO, CM, CM, CM, CM, MM, MM, MM,
            0.25f, 13.0f, -1.0f, nullptr, nullptr, 0, 0, -1);
        bf16* tmp = zc; zc = zn; zn = tmp;
    }

    // --- s0 window: full QKV projection, a1, flash, conv ---
    tc_gemm<128, 256, 2, 4, 1, false, 1><<<dim3(6, CB * CN / 128, 1), 256>>>(
        xn, wq16, nullptr, CD, CD, CT3, 0, 0, 0, 0,
        1.0f, 0.0f, 1.0f, nullptr, nullptr, 0, 0, -1);
    tc_gemm<128, 256, 2, 4, 3, false, 1><<<dim3(1, CN / 128, CBH), 256>>>(
        q, klT, a1, CDH, CDH, CM, CM,
        NDH, (size_t)CDH * CM, (size_t)CN * CM, 1.0f, 0.0f, 1.0f,
        nullptr, nullptr, 0, 0, -1);
    flash_av<<<dim3(CM / 128, CBH), 256>>>();
    conv_res<<<(CBH * CN * CDH) / 1024, 256>>>(convw);
    cudaEventRecord(g_aux.evAV, 0);

    // --- zav halves on s1/s2 ---
    cudaStreamWaitEvent(s1, g_aux.evAV, 0);
    tc_gemm<64, 64, 4, 2, 0, false, 2><<<dim3(1, CM / 64, 16), 256, 0, s1>>>(
        zc, av, zav, CM, CM, CDH, CDH,
        MM, (size_t)CM * CDH, (size_t)CM * CDH, 1.0f, 0.0f, 1.0f,
        nullptr, nullptr, 0, 0, -1);
    cudaEventRecord(g_aux.evJ, s1);
    cudaStreamWaitEvent(s2, g_aux.evAV, 0);
    tc_gemm<64, 64, 4, 2, 0, false, 2><<<dim3(1, CM / 64, 16), 256, 0, s2>>>(
        zc + HO, av + AVH, zav + AVH, CM, CM, CDH, CDH,
        MM, (size_t)CM * CDH, (size_t)CM * CDH, 1.0f, 0.0f, 1.0f,
        nullptr, nullptr, 0, 0, -1);
    cudaEventRecord(g_aux.evJ2, s2);

    // --- pipelined tail ---
    cudaStreamWaitEvent(0, g_aux.evJ, 0);
    cudaStreamWaitEvent(0, g_aux.evJ2, 0);
    tc_gemm<128, 64, 4, 2, 4, false, 2><<<dim3(1, 16, CBH), 256>>>(
        a1, zav, outh, CM, CM, CDH, CDH,
        (size_t)CN * CM, (size_t)CM * CDH, NDH, 1.0f, 0.0f, 1.0f,
        nullptr, nullptr, 0, 0, -1);
    cudaStreamWaitEvent(s1, g_aux.evJ2, 0);
    tc_gemm<128, 64, 4, 2, 4, false, 2><<<dim3(1, 16, CBH), 256, 0, s1>>>(
        a1, zav, outh, CM, CM, CDH, CDH,
        (size_t)CN * CM, (size_t)CM * CDH, NDH, 1.0f, 0.0f, 1.0f,
        nullptr, nullptr, 0, 16, -1);
    cudaEventRecord(g_aux.evO2, s1);
    tc_gemm<128, 256, 2, 4, 2, false, 1><<<dim3(CD / 256, 64, 1), 256>>>(
        outh, wo16, out, CD, 0, CD, CD, 0, 0, 0, 1.0f, 0.0f, 1.0f,
        x, bout, 0, 0, 0);
    cudaStreamWaitEvent(0, g_aux.evO2, 0);
    tc_gemm<128, 256, 2, 4, 2, false, 1><<<dim3(CD / 256, 64, 1), 256>>>(
        outh, wo16, out, CD, 0, CD, CD, 0, 0, 0, 1.0f, 0.0f, 1.0f,
        x, bout, 0, 0, 1);
}

// round 16
// speedup vs baseline: 1.0549x; 1.0549x over previous
#include <cuda_runtime.h>
#include <cuda_bf16.h>
#include <math.h>
#include <stdint.h>

constexpr int CB  = 4;
constexpr int CN  = 4096;
constexpr int CD  = 512;
constexpr int CH  = 8;
constexpr int CDH = 64;
constexpr int CM  = 256;
constexpr int CL  = 16;
constexpr int CBH = CB * CH;    // 32
constexpr int CT3 = 3 * CD;     // 1536
constexpr float EPS = 1e-5f;

typedef __nv_bfloat16 bf16;
typedef __nv_bfloat162 bf162;

// ---------------------------------------------------------------------------
// Device scratch
// ---------------------------------------------------------------------------
__device__ __align__(16) bf16 g_xn  [(size_t)CB * CN * CD];
__device__ __align__(16) bf16 g_q   [(size_t)CBH * CN * CDH];
__device__ __align__(16) bf16 g_v   [(size_t)CBH * CN * CDH];
__device__ __align__(16) bf16 g_kT  [(size_t)CBH * CDH * CN];
__device__ __align__(16) bf16 g_ql  [(size_t)CBH * CM * CDH];
__device__ __align__(16) bf16 g_klT [(size_t)CBH * CDH * CM];
__device__ __align__(16) bf16 g_a1  [(size_t)CBH * CN * CM];
__device__ __align__(16) bf16 g_a2  [(size_t)CBH * CM * CM];
__device__ __align__(16) bf16 g_z   [(size_t)CBH * CM * CM];
__device__ __align__(16) bf16 g_z2  [(size_t)CBH * CM * CM];
__device__ __align__(16) bf16 g_xz  [(size_t)CBH * CM * CM];
__device__ __align__(16) bf16 g_t   [(size_t)CBH * CM * CM];
__device__ __align__(16) bf16 g_u   [(size_t)CBH * CM * CM];
__device__ __align__(16) bf16 g_av  [(size_t)CBH * CM * CDH];
__device__ __align__(16) bf16 g_zav [(size_t)CBH * CM * CDH];
__device__ __align__(16) bf16 g_outh[(size_t)CBH * CN * CDH];
__device__ __align__(16) bf16 g_wq16[(size_t)CD * CT3];
__device__ __align__(16) bf16 g_wo16[(size_t)CD * CD];
__device__ unsigned g_maxc, g_maxr;

// ---------------------------------------------------------------------------
// Fork/join resources (host-side only; created once at static init)
// ---------------------------------------------------------------------------
struct AuxStreams {
    cudaStream_t s1, s2;
    cudaEvent_t evF, evZ, evAV, evJ, evJ2, evO2;
    AuxStreams() {
        cudaStreamCreateWithFlags(&s1, cudaStreamNonBlocking);
        cudaStreamCreateWithFlags(&s2, cudaStreamNonBlocking);
        cudaEventCreateWithFlags(&evF,  cudaEventDisableTiming);
        cudaEventCreateWithFlags(&evZ,  cudaEventDisableTiming);
        cudaEventCreateWithFlags(&evAV, cudaEventDisableTiming);
        cudaEventCreateWithFlags(&evJ,  cudaEventDisableTiming);
        cudaEventCreateWithFlags(&evJ2, cudaEventDisableTiming);
        cudaEventCreateWithFlags(&evO2, cudaEventDisableTiming);
    }
};
static AuxStreams g_aux;

// ---------------------------------------------------------------------------
// helpers
// ---------------------------------------------------------------------------
__device__ __forceinline__ uint32_t pack2(float a, float b) {
    bf162 h = __floats2bfloat162_rn(a, b);
    return *reinterpret_cast<uint32_t*>(&h);
}
__device__ __forceinline__ float2 unpk(uint32_t u) {
    bf162 h = *reinterpret_cast<bf162*>(&u);
    return __bfloat1622float2(h);
}
__device__ __forceinline__ void mma16(float* c, const uint32_t* a,
                                      uint32_t b0, uint32_t b1) {
    asm volatile(
        "mma.sync.aligned.m16n8k16.row.col.f32.bf16.bf16.f32 "
        "{%0,%1,%2,%3},{%4,%5,%6,%7},{%8,%9},{%0,%1,%2,%3};"
        : "+f"(c[0]), "+f"(c[1]), "+f"(c[2]), "+f"(c[3])
        : "r"(a[0]), "r"(a[1]), "r"(a[2]), "r"(a[3]), "r"(b0), "r"(b1));
}
__device__ __forceinline__ void ldsm4(uint32_t* r, uint32_t addr) {
    asm volatile(
        "ldmatrix.sync.aligned.m8n8.x4.shared.b16 {%0,%1,%2,%3},[%4];"
        : "=r"(r[0]), "=r"(r[1]), "=r"(r[2]), "=r"(r[3]) : "r"(addr));
}
__device__ __forceinline__ void ldsm4t(uint32_t& r0, uint32_t& r1,
                                       uint32_t& r2, uint32_t& r3, uint32_t addr) {
    asm volatile(
        "ldmatrix.sync.aligned.m8n8.x4.trans.shared.b16 {%0,%1,%2,%3},[%4];"
        : "=r"(r0), "=r"(r1), "=r"(r2), "=r"(r3) : "r"(addr));
}

// ---------------------------------------------------------------------------
// bf16 tensor-core batched GEMM.  C = alpha * A @ (diagc*I + bsign*B)
// MODE 0: bf16 store  1: QKV scatter  2: final fp32 (+X+bias, gather A)
// MODE 3: fused row softmax (BN == row width)  4: bf16 accumulate
// xoff: column-block offset.  yoff: row-block offset.
// ysplit >= 0: row-block mapping by = (y/16)*32 + (y%16) + ysplit*16
// ---------------------------------------------------------------------------
template <int BM, int BN, int WGM, int WGN, int MODE, bool DIAG, int MINB>
__global__ __launch_bounds__(256, MINB)
void tc_gemm(const bf16* __restrict__ A, const bf16* __restrict__ B,
             void* __restrict__ Cp,
             int K, int lda, int ldb, int ldc,
             size_t sA, size_t sB, size_t sC,
             float alpha, float diagc, float bsign,
             const float* __restrict__ X, const float* __restrict__ bias,
             int xoff, int yoff, int ysplit) {
    constexpr int WROWS = BM / WGM;
    constexpr int WCOLS = BN / WGN;
    constexpr int MI    = WROWS / 16;
    constexpr int NFR   = WCOLS / 8;
    constexpr int TPRA  = 256 / BM;
    constexpr int KSPAN = 32 / TPRA;
    constexpr int NU4   = KSPAN / 8;
    constexpr int TPRB  = BN / 8;
    constexpr int RPPB  = 256 / TPRB;
    constexpr int BPASS = 32 / RPPB;
    constexpr int AP    = 40;
    constexpr int BPH   = BN + 8;

    __shared__ bf16 As[BM * AP];
    __shared__ bf16 Bs[32 * BPH];
    __shared__ float sred[(MODE == 3) ? 2 * BM * WGN : 2];

    const int t = threadIdx.x, warp = t >> 5, lane = t & 31;
    const int wm = warp / WGN, wn = warp % WGN;
    const int g = lane >> 2, tg = lane & 3;
    int by = blockIdx.y + yoff;
    if (ysplit >= 0)
        by = ((blockIdx.y >> 4) << 5) + (blockIdx.y & 15) + ysplit * 16;
    const int rowBase = by * BM;
    const int colBase = (blockIdx.x + xoff) * BN;
    const int arow = t % BM, akg = (t / BM) * KSPAN;
    const int brow = t / TPRB, bcol = (t % TPRB) * 8;

    const bf16* Ab = A + blockIdx.z * sA;
    const bf16* Bb = B + blockIdx.z * sB;

    const uint32_t asb = (uint32_t)__cvta_generic_to_shared(As);
    const uint32_t bsb = (uint32_t)__cvta_generic_to_shared(Bs);
    const uint32_t aoff = asb +
        ((((lane >> 3) & 1) * 8 + (lane & 7)) * AP + (lane >> 4) * 8) * 2;
    const uint32_t boff = bsb +
        ((((lane >> 3) & 1) * 8 + (lane & 7)) * BPH + wn * WCOLS + (lane >> 4) * 8) * 2;

    uint4 pa[NU4];
    uint4 pbb[BPASS];

    auto ldA = [&](int k0) {
        if (MODE == 2) {
            int r = rowBase + arow;
            int b_ = r >> 12, n = r & (CN - 1);
            int c = k0 + akg;
            int h_ = c >> 6, dh = c & 63;
            const bf16* p = Ab + ((((size_t)(b_ * CH + h_)) * CN + n) * CDH + dh);
#pragma unroll
            for (int i = 0; i < NU4; i++) pa[i] = *(const uint4*)(p + i * 8);
        } else {
            const bf16* p = Ab + (size_t)(rowBase + arow) * lda + k0 + akg;
#pragma unroll
            for (int i = 0; i < NU4; i++) pa[i] = *(const uint4*)(p + i * 8);
        }
    };
    auto ldB = [&](int k0) {
#pragma unroll
        for (int i = 0; i < BPASS; i++)
            pbb[i] = *(const uint4*)(Bb + (size_t)(k0 + brow + i * RPPB) * ldb +
                                     colBase + bcol);
    };
    auto stage = [&](int k0) {
#pragma unroll
        for (int i = 0; i < NU4; i++)
            *(uint4*)&As[arow * AP + akg + i * 8] = pa[i];
#pragma unroll
        for (int i = 0; i < BPASS; i++) {
            int r = brow + i * RPPB;
            uint4 u;
            if (DIAG) {
                float e[8];
                float2 f;
                f = unpk(pbb[i].x); e[0] = f.x; e[1] = f.y;
                f = unpk(pbb[i].y); e[2] = f.x; e[3] = f.y;
                f = unpk(pbb[i].z); e[4] = f.x; e[5] = f.y;
                f = unpk(pbb[i].w); e[6] = f.x; e[7] = f.y;
                int kr = k0 + r;
                int cb = colBase + bcol;
#pragma unroll
                for (int j = 0; j < 8; j++)
                    e[j] = bsign * e[j] + ((kr == cb + j) ? diagc : 0.0f);
                u.x = pack2(e[0], e[1]); u.y = pack2(e[2], e[3]);
                u.z = pack2(e[4], e[5]); u.w = pack2(e[6], e[7]);
            } else {
                u = pbb[i];
            }
            *(uint4*)&Bs[r * BPH + bcol] = u;
        }
    };

    float acc[MI][NFR][4] = {};

    ldA(0); ldB(0); stage(0);
    __syncthreads();
    for (int k0 = 0;; k0 += 32) {
        const int kn = k0 + 32;
        const bool more = kn < K;
        if (more) { ldA(kn); ldB(kn); }
#pragma unroll
        for (int ks = 0; ks < 2; ks++) {
            uint32_t af[MI][4];
#pragma unroll
            for (int mi = 0; mi < MI; mi++)
                ldsm4(af[mi], aoff + ((wm * WROWS + mi * 16) * AP + ks * 16) * 2);
            uint32_t bfr[NFR][2];
#pragma unroll
            for (int np = 0; np < NFR / 2; np++)
                ldsm4t(bfr[2 * np][0], bfr[2 * np][1],
                       bfr[2 * np + 1][0], bfr[2 * np + 1][1],
                       boff + (ks * 16 * BPH + np * 16) * 2);
#pragma unroll
            for (int ni = 0; ni < NFR; ni++)
#pragma unroll
                for (int mi = 0; mi < MI; mi++)
                    mma16(acc[mi][ni], af[mi], bfr[ni][0], bfr[ni][1]);
        }
        if (!more) break;
        __syncthreads();
        stage(kn);
        __syncthreads();
    }

    bf16*  Cb16 = (bf16*)Cp + blockIdx.z * sC;
    float* Cbf  = (float*)Cp + blockIdx.z * sC;

    if (MODE == 3) {
        float* smax = sred;
        float* ssum = sred + BM * WGN;
#pragma unroll
        for (int mi = 0; mi < MI; mi++)
#pragma unroll
            for (int h2 = 0; h2 < 2; h2++) {
                float m = -3.4e38f;
#pragma unroll
                for (int ni = 0; ni < NFR; ni++) {
                    m = fmaxf(m, acc[mi][ni][h2 * 2]);
                    m = fmaxf(m, acc[mi][ni][h2 * 2 + 1]);
                }
                m = fmaxf(m, __shfl_xor_sync(0xffffffffu, m, 1));
                m = fmaxf(m, __shfl_xor_sync(0xffffffffu, m, 2));
                int rl = wm * WROWS + mi * 16 + h2 * 8 + g;
                if (tg == 0) smax[rl * WGN + wn] = m;
            }
        __syncthreads();
#pragma unroll
        for (int mi = 0; mi < MI; mi++)
#pragma unroll
            for (int h2 = 0; h2 < 2; h2++) {
                int rl = wm * WROWS + mi * 16 + h2 * 8 + g;
                float tm = smax[rl * WGN];
#pragma unroll
                for (int w = 1; w < WGN; w++) tm = fmaxf(tm, smax[rl * WGN + w]);
                float s = 0.0f;
#pragma unroll
                for (int ni = 0; ni < NFR; ni++) {
                    float e0 = __expf(acc[mi][ni][h2 * 2]     - tm);
                    float e1 = __expf(acc[mi][ni][h2 * 2 + 1] - tm);
                    acc[mi][ni][h2 * 2]     = e0;
                    acc[mi][ni][h2 * 2 + 1] = e1;
                    s += e0 + e1;
                }
                s += __shfl_xor_sync(0xffffffffu, s, 1);
                s += __shfl_xor_sync(0xffffffffu, s, 2);
                if (tg == 0) ssum[rl * WGN + wn] = s;
            }
        __syncthreads();
#pragma unroll
        for (int mi = 0; mi < MI; mi++)
#pragma unroll
            for (int h2 = 0; h2 < 2; h2++) {
                int rl = wm * WROWS + mi * 16 + h2 * 8 + g;
                float s = 0.0f;
#pragma unroll
                for (int w = 0; w < WGN; w++) s += ssum[rl * WGN + w];
                float inv = 1.0f / s;
                int r = rowBase + rl;
#pragma unroll
                for (int ni = 0; ni < NFR; ni++) {
                    int c0 = colBase + wn * WCOLS + ni * 8 + 2 * tg;
                    *(uint32_t*)&Cb16[(size_t)r * ldc + c0] =
                        pack2(acc[mi][ni][h2 * 2] * inv,
                              acc[mi][ni][h2 * 2 + 1] * inv);
                }
            }
        return;
    }

#pragma unroll
    for (int mi = 0; mi < MI; mi++)
#pragma unroll
        for (int ni = 0; ni < NFR; ni++) {
            int r0 = rowBase + wm * WROWS + mi * 16 + g;
            int c0 = colBase + wn * WCOLS + ni * 8 + 2 * tg;
#pragma unroll
            for (int h2 = 0; h2 < 2; h2++) {
                int r = r0 + h2 * 8;
                float vx = alpha * acc[mi][ni][h2 * 2];
                float vy = alpha * acc[mi][ni][h2 * 2 + 1];
                if (MODE == 0) {
                    *(uint32_t*)&Cb16[(size_t)r * ldc + c0] = pack2(vx, vy);
                } else if (MODE == 4) {
                    uint32_t old = *(uint32_t*)&Cb16[(size_t)r * ldc + c0];
                    float2 f = unpk(old);
                    *(uint32_t*)&Cb16[(size_t)r * ldc + c0] =
                        pack2(vx + f.x, vy + f.y);
                } else if (MODE == 1) {
                    int b_ = r >> 12, n = r & (CN - 1);
                    int which = c0 >> 9, inner = c0 & 511;
                    int h_ = inner >> 6, dh = inner & 63;
                    size_t off = (((size_t)(b_ * CH + h_)) * CN + n) * CDH + dh;
                    if (which == 0) {
                        *(uint32_t*)&g_q[off] = pack2(vx * 0.125f, vy * 0.125f);
                    } else if (which == 1) {
                        size_t ot = (((size_t)(b_ * CH + h_)) * CDH + dh) * CN + n;
                        g_kT[ot]      = __float2bfloat16(vx);
                        g_kT[ot + CN] = __float2bfloat16(vy);
                    } else {
                        *(uint32_t*)&g_v[off] = pack2(vx, vy);
                    }
                } else {
                    size_t o = (size_t)r * CD + c0;
                    float2 xr = *(const float2*)&X[o];
                    float2 br = *(const float2*)&bias[c0];
                    *(float2*)&Cbf[o] = make_float2(vx + xr.x + br.x,
                                                    vy + xr.y + br.y);
                }
            }
        }
}

// ---------------------------------------------------------------------------
// Flash kernel: av = softmax_rows(ql @ k^T) @ v   (per bh, 128 m-rows/CTA)
// ---------------------------------------------------------------------------
__global__ __launch_bounds__(256, 1)
void flash_av() {
    constexpr int KP = 136;
    constexpr int VP = 72;
    __shared__ bf16 Ks[64 * KP];
    __shared__ bf16 Vs[128 * VP];

    const int t = threadIdx.x, warp = t >> 5, lane = t & 31;
    const int g = lane >> 2, tg = lane & 3;
    const int mb = blockIdx.x, bh = blockIdx.y;

    const bf16* qlb = g_ql + ((size_t)bh * CM + mb * 128) * CDH;
    const bf16* kTb = g_kT + (size_t)bh * CDH * CN;
    const bf16* vb  = g_v  + (size_t)bh * CN * CDH;

    const uint32_t ksb = (uint32_t)__cvta_generic_to_shared(Ks);
    const uint32_t vsb = (uint32_t)__cvta_generic_to_shared(Vs);
    const int rsel = ((lane >> 3) & 1) * 8 + (lane & 7);
    const int csel = (lane >> 4) * 8;

    for (int i = t; i < 1024; i += 256) {
        int row = i >> 3, cg = i & 7;
        *(uint4*)&Vs[row * VP + cg * 8] = *(const uint4*)&qlb[row * CDH + cg * 8];
    }
    __syncthreads();
    uint32_t qlA[4][4];
    {
        uint32_t base = vsb + ((warp * 16 + rsel) * VP + csel) * 2;
#pragma unroll
        for (int kb = 0; kb < 4; kb++) ldsm4(qlA[kb], base + kb * 16 * 2);
    }
    __syncthreads();

    float oacc[8][4] = {};
    float m0 = -1e30f, m1 = -1e30f, l0 = 0.0f, l1 = 0.0f;

    for (int ch = 0; ch < CN / 128; ch++) {
        for (int i = t; i < 1024; i += 256) {
            int row = i >> 4, cg = i & 15;
            *(uint4*)&Ks[row * KP + cg * 8] =
                *(const uint4*)&kTb[(size_t)row * CN + ch * 128 + cg * 8];
        }
        for (int i = t; i < 1024; i += 256) {
            int row = i >> 3, cg = i & 7;
            *(uint4*)&Vs[row * VP + cg * 8] =
                *(const uint4*)&vb[(size_t)(ch * 128 + row) * CDH + cg * 8];
        }
        __syncthreads();

        float sacc[16][4] = {};
#pragma unroll
        for (int ks = 0; ks < 4; ks++) {
            uint32_t brow = ksb + ((ks * 16 + rsel) * KP + csel) * 2;
#pragma unroll
            for (int np = 0; np < 8; np++) {
                uint32_t b0, b1, b2, b3;
                ldsm4t(b0, b1, b2, b3, brow + np * 16 * 2);
                mma16(sacc[2 * np],     qlA[ks], b0, b1);
                mma16(sacc[2 * np + 1], qlA[ks], b2, b3);
            }
        }

        float mx0 = m0, mx1 = m1;
#pragma unroll
        for (int ni = 0; ni < 16; ni++) {
            mx0 = fmaxf(mx0, fmaxf(sacc[ni][0], sacc[ni][1]));
            mx1 = fmaxf(mx1, fmaxf(sacc[ni][2], sacc[ni][3]));
        }
        mx0 = fmaxf(mx0, __shfl_xor_sync(0xffffffffu, mx0, 1));
        mx0 = fmaxf(mx0, __shfl_xor_sync(0xffffffffu, mx0, 2));
        mx1 = fmaxf(mx1, __shfl_xor_sync(0xffffffffu, mx1, 1));
        mx1 = fmaxf(mx1, __shfl_xor_sync(0xffffffffu, mx1, 2));
        float r0 = __expf(m0 - mx0), r1 = __expf(m1 - mx1);
        m0 = mx0; m1 = mx1;
        float s0 = 0.0f, s1 = 0.0f;
#pragma unroll
        for (int ni = 0; ni < 16; ni++) {
            sacc[ni][0] = __expf(sacc[ni][0] - m0);
            sacc[ni][1] = __expf(sacc[ni][1] - m0);
            sacc[ni][2] = __expf(sacc[ni][2] - m1);
            sacc[ni][3] = __expf(sacc[ni][3] - m1);
            s0 += sacc[ni][0] + sacc[ni][1];
            s1 += sacc[ni][2] + sacc[ni][3];
        }
        s0 += __shfl_xor_sync(0xffffffffu, s0, 1);
        s0 += __shfl_xor_sync(0xffffffffu, s0, 2);
        s1 += __shfl_xor_sync(0xffffffffu, s1, 1);
        s1 += __shfl_xor_sync(0xffffffffu, s1, 2);
        l0 = l0 * r0 + s0;
        l1 = l1 * r1 + s1;
#pragma unroll
        for (int f = 0; f < 8; f++) {
            oacc[f][0] *= r0; oacc[f][1] *= r0;
            oacc[f][2] *= r1; oacc[f][3] *= r1;
        }

#pragma unroll
        for (int kb = 0; kb < 8; kb++) {
            uint32_t pA[4];
            pA[0] = pack2(sacc[2 * kb][0],     sacc[2 * kb][1]);
            pA[1] = pack2(sacc[2 * kb][2],     sacc[2 * kb][3]);
            pA[2] = pack2(sacc[2 * kb + 1][0], sacc[2 * kb + 1][1]);
            pA[3] = pack2(sacc[2 * kb + 1][2], sacc[2 * kb + 1][3]);
            uint32_t vrow = vsb + ((kb * 16 + rsel) * VP + csel) * 2;
#pragma unroll
            for (int np = 0; np < 4; np++) {
                uint32_t b0, b1, b2, b3;
                ldsm4t(b0, b1, b2, b3, vrow + np * 16 * 2);
                mma16(oacc[2 * np],     pA, b0, b1);
                mma16(oacc[2 * np + 1], pA, b2, b3);
            }
        }
        __syncthreads();
    }

    float inv0 = 1.0f / l0, inv1 = 1.0f / l1;
    int row0 = mb * 128 + warp * 16 + g;
    bf16* avb = g_av + ((size_t)bh * CM) * CDH;
#pragma unroll
    for (int f = 0; f < 8; f++) {
        int c0 = f * 8 + 2 * tg;
        *(uint32_t*)&avb[(size_t)row0 * CDH + c0] =
            pack2(oacc[f][0] * inv0, oacc[f][1] * inv0);
        *(uint32_t*)&avb[(size_t)(row0 + 8) * CDH + c0] =
            pack2(oacc[f][2] * inv1, oacc[f][3] * inv1);
    }
}

// ---------------------------------------------------------------------------
__global__ void convert_w(const float* __restrict__ Wqkv,
                          const float* __restrict__ Wout) {
    int i = (blockIdx.x * 256 + threadIdx.x) * 4;
    const int n1 = CD * CT3;
    if (i < n1) {
        float4 v = *(const float4*)&Wqkv[i];
        uint2 o; o.x = pack2(v.x, v.y); o.y = pack2(v.z, v.w);
        *(uint2*)&g_wq16[i] = o;
    }
    if (i < CD * CD) {
        float4 v = *(const float4*)&Wout[i];
        uint2 o; o.x = pack2(v.x, v.y); o.y = pack2(v.z, v.w);
        *(uint2*)&g_wo16[i] = o;
    }
}

__global__ void ln_kernel(const float* __restrict__ x,
                          const float* __restrict__ gamma,
                          const float* __restrict__ beta) {
    int row = blockIdx.x;
    int t = threadIdx.x;
    const float4* xr = (const float4*)(x + (size_t)row * CD);
    float4 v = xr[t];
    float s  = v.x + v.y + v.z + v.w;
    float ss = v.x * v.x + v.y * v.y + v.z * v.z + v.w * v.w;
    __shared__ float shs[4], shss[4];
#pragma unroll
    for (int o = 16; o > 0; o >>= 1) {
        s  += __shfl_down_sync(0xffffffffu, s,  o);
        ss += __shfl_down_sync(0xffffffffu, ss, o);
    }
    int wid = t >> 5, lane = t & 31;
    if (!lane) { shs[wid] = s; shss[wid] = ss; }
    __syncthreads();
    s  = shs[0]  + shs[1]  + shs[2]  + shs[3];
    ss = shss[0] + shss[1] + shss[2] + shss[3];
    float mean = s * (1.0f / CD);
    float var  = ss * (1.0f / CD) - mean * mean;
    float inv  = rsqrtf(var + EPS);
    float4 gg = ((const float4*)gamma)[t];
    float4 bb = ((const float4*)beta)[t];
    uint2 o;
    o.x = pack2((v.x - mean) * inv * gg.x + bb.x, (v.y - mean) * inv * gg.y + bb.y);
    o.y = pack2((v.z - mean) * inv * gg.z + bb.z, (v.w - mean) * inv * gg.w + bb.w);
    *(uint2*)&g_xn[(size_t)row * CD + t * 4] = o;
}

__global__ void landmark_kernel() {
    int idx = blockIdx.x * 256 + threadIdx.x;
    int dh = idx & 63;
    int mi = (idx >> 6) & 255;
    int bh = idx >> 14;
    size_t qbase = ((size_t)bh * CN + mi * CL) * CDH + dh;
    float sq = 0.0f;
#pragma unroll
    for (int j = 0; j < CL; j++)
        sq += __bfloat162float(g_q[qbase + (size_t)j * CDH]);
    size_t kbase = ((size_t)bh * CDH + dh) * CN + mi * CL;
    float sk = 0.0f;
#pragma unroll
    for (int j = 0; j < CL; j++)
        sk += __bfloat162float(g_kT[kbase + j]);
    g_ql [((size_t)bh * CM + mi) * CDH + dh] = __float2bfloat16(sq * (1.0f / CL));
    g_klT[((size_t)bh * CDH + dh) * CM + mi] = __float2bfloat16(sk * (1.0f / CL));
}

__global__ void init_scalars() { g_maxc = 0u; g_maxr = 0u; }

// Coalesced absmax: col sums per-thread (coalesced); row sums warp-per-row.
__global__ void absmax_sums() {
    int bh = blockIdx.x;
    int t = threadIdx.x, warp = t >> 5, lane = t & 31;
    const bf16* a = g_a2 + (size_t)bh * CM * CM;
    float cs = 0.0f;
    for (int i = 0; i < CM; i++)
        cs += fabsf(__bfloat162float(a[(size_t)i * CM + t]));
    atomicMax(&g_maxr, __float_as_uint(cs));
    float rm = 0.0f;
    for (int r = warp; r < CM; r += 8) {
        float s = 0.0f;
        for (int c = lane; c < CM; c += 32)
            s += fabsf(__bfloat162float(a[(size_t)r * CM + c]));
#pragma unroll
        for (int o = 16; o > 0; o >>= 1) s += __shfl_xor_sync(0xffffffffu, s, o);
        rm = fmaxf(rm, s);
    }
    if (lane == 0) atomicMax(&g_maxc, __float_as_uint(rm));
}

// Coalesced transposed init: z[i][j] = a2[j][i] / denom via 32x32 smem tiles.
__global__ void zinit_kernel() {
    __shared__ float tile[32][33];
    int bh = blockIdx.z;
    int i0 = blockIdx.x * 32, j0 = blockIdx.y * 32;
    int tx = threadIdx.x, ty = threadIdx.y;   // 32 x 8
    size_t b = (size_t)bh << 16;
    float inv = 1.0f / (__uint_as_float(g_maxc) * __uint_as_float(g_maxr));
#pragma unroll
    for (int k = 0; k < 4; k++) {
        int row = ty + k * 8;
        tile[row][tx] = __bfloat162float(g_a2[b + (size_t)(j0 + row) * CM + i0 + tx]);
    }
    __syncthreads();
#pragma unroll
    for (int k = 0; k < 4; k++) {
        int row = ty + k * 8;
        g_z[b + (size_t)(i0 + row) * CM + j0 + tx] =
            __float2bfloat16(tile[tx][row] * inv);
    }
}

__global__ void conv_res(const float* __restrict__ w) {
    __shared__ float ws[33];
    int idx = blockIdx.x * 256 + threadIdx.x;
    int dh = idx & 63;
    int nq = (idx >> 6) & 1023;
    int bh = idx >> 16;
    int h_ = bh & 7;
    if (threadIdx.x < 33) ws[threadIdx.x] = w[h_ * 33 + threadIdx.x];
    __syncthreads();
    int n0 = nq * 4;
    size_t base = ((size_t)bh * CN) * CDH + dh;
    float vv[36];
#pragma unroll
    for (int j = 0; j < 36; j++) {
        int nn = n0 - 16 + j;
        vv[j] = (nn >= 0 && nn < CN)
                    ? __bfloat162float(g_v[base + (size_t)nn * CDH]) : 0.0f;
    }
#pragma unroll
    for (int i = 0; i < 4; i++) {
        float s = 0.0f;
#pragma unroll
        for (int k2 = 0; k2 < 33; k2++) s += ws[k2] * vv[k2 + i];
        g_outh[base + (size_t)(n0 + i) * CDH] = __float2bfloat16(s);
    }
}

// ---------------------------------------------------------------------------
// Launch (round-14 schedule; coalesced absmax/zinit on critical path)
// ---------------------------------------------------------------------------
extern "C" void kernel_launch(void* const* d_in, const int* in_sizes, int n_in,
                              void* d_out, int out_size) {
    const float* x     = (const float*)d_in[0];
    const float* gamma = (const float*)d_in[1];
    const float* beta  = (const float*)d_in[2];
    const float* Wqkv  = (const float*)d_in[3];
    const float* Wout  = (const float*)d_in[4];
    const float* bout  = (const float*)d_in[5];
    const float* convw = (const float*)d_in[6];
    float* out = (float*)d_out;

    bf16 *xn, *q, *v, *kT, *ql, *klT, *a1, *a2;
    bf16 *z, *z2, *xz, *tb, *ub, *av, *zav, *outh, *wq16, *wo16;
    void* p;
    cudaGetSymbolAddress(&p, g_xn);   xn   = (bf16*)p;
    cudaGetSymbolAddress(&p, g_q);    q    = (bf16*)p;
    cudaGetSymbolAddress(&p, g_v);    v    = (bf16*)p;
    cudaGetSymbolAddress(&p, g_kT);   kT   = (bf16*)p;
    cudaGetSymbolAddress(&p, g_ql);   ql   = (bf16*)p;
    cudaGetSymbolAddress(&p, g_klT);  klT  = (bf16*)p;
    cudaGetSymbolAddress(&p, g_a1);   a1   = (bf16*)p;
    cudaGetSymbolAddress(&p, g_a2);   a2   = (bf16*)p;
    cudaGetSymbolAddress(&p, g_z);    z    = (bf16*)p;
    cudaGetSymbolAddress(&p, g_z2);   z2   = (bf16*)p;
    cudaGetSymbolAddress(&p, g_xz);   xz   = (bf16*)p;
    cudaGetSymbolAddress(&p, g_t);    tb   = (bf16*)p;
    cudaGetSymbolAddress(&p, g_u);    ub   = (bf16*)p;
    cudaGetSymbolAddress(&p, g_av);   av   = (bf16*)p;
    cudaGetSymbolAddress(&p, g_zav);  zav  = (bf16*)p;
    cudaGetSymbolAddress(&p, g_outh); outh = (bf16*)p;
    cudaGetSymbolAddress(&p, g_wq16); wq16 = (bf16*)p;
    cudaGetSymbolAddress(&p, g_wo16); wo16 = (bf16*)p;

    const size_t MM  = (size_t)CM * CM;
    const size_t NDH = (size_t)CN * CDH;
    const size_t AVH = (size_t)16 * CM * CDH;
    cudaStream_t s1 = g_aux.s1, s2 = g_aux.s2;
    const size_t HO = (size_t)16 * MM;

    // --- s0 prefix: LN, weights, QK projection (cols 0..1023), landmark ---
    ln_kernel<<<CB * CN, 128>>>(x, gamma, beta);
    convert_w<<<(CD * CT3) / 1024, 256>>>(Wqkv, Wout);
    tc_gemm<128, 256, 2, 4, 1, false, 1><<<dim3(4, CB * CN / 128, 1), 256>>>(
        xn, wq16, nullptr, CD, CD, CT3, 0, 0, 0, 0,
        1.0f, 0.0f, 1.0f, nullptr, nullptr, 0, 0, -1);
    landmark_kernel<<<(CBH * CM * CDH) / 256, 256>>>();
    cudaEventRecord(g_aux.evF, 0);

    // --- s1: a2 + pinv init + half-chain bh 0-15 (critical path) ---
    cudaStreamWaitEvent(s1, g_aux.evF, 0);
    tc_gemm<128, 256, 2, 4, 3, false, 1><<<dim3(1, CM / 128, CBH), 256, 0, s1>>>(
        ql, klT, a2, CDH, CDH, CM, CM,
        (size_t)CM * CDH, (size_t)CDH * CM, MM, 1.0f, 0.0f, 1.0f,
        nullptr, nullptr, 0, 0, -1);
    init_scalars<<<1, 1, 0, s1>>>();
    absmax_sums<<<CBH, 256, 0, s1>>>();
    zinit_kernel<<<dim3(CM / 32, CM / 32, CBH), dim3(32, 8), 0, s1>>>();
    cudaEventRecord(g_aux.evZ, s1);
    cudaStreamWaitEvent(s2, g_aux.evZ, 0);

    bf16* zc = z;
    bf16* zn = z2;
    for (int it = 0; it < 5; it++) {
        tc_gemm<128, 256, 2, 4, 0, false, 1><<<dim3(1, 2, 16), 256, 0, s1>>>(
            a2, zc, xz, CM, CM, CM, CM, MM, MM, MM, 1.0f, 0.0f, 1.0f,
            nullptr, nullptr, 0, 0, -1);
        tc_gemm<128, 256, 2, 4, 0, true, 1><<<dim3(1, 2, 16), 256, 0, s1>>>(
            xz, xz, tb, CM, CM, CM, CM, MM, MM, MM, 1.0f, 7.0f, -1.0f,
            nullptr, nullptr, 0, 0, -1);
        tc_gemm<128, 256, 2, 4, 0, true, 1><<<dim3(1, 2, 16), 256, 0, s1>>>(
            xz, tb, ub, CM, CM, CM, CM, MM, MM, MM, 1.0f, 15.0f, -1.0f,
            nullptr, nullptr, 0, 0, -1);
        tc_gemm<128, 256, 2, 4, 0, true, 1><<<dim3(1, 2, 16), 256, 0, s1>>>(
            zc, ub, zn, CM, CM, CM, CM, MM, MM, MM, 0.25f, 13.0f, -1.0f,
            nullptr, nullptr, 0, 0, -1);
        tc_gemm<128, 256, 2, 4, 0, false, 1><<<dim3(1, 2, 16), 256, 0, s2>>>(
            a2 + HO, zc + HO, xz + HO, CM, CM, CM, CM, MM, MM, MM,
            1.0f, 0.0f, 1.0f, nullptr, nullptr, 0, 0, -1);
        tc_gemm<128, 256, 2, 4, 0, true, 1><<<dim3(1, 2, 16), 256, 0, s2>>>(
            xz + HO, xz + HO, tb + HO, CM, CM, CM, CM, MM, MM, MM,
            1.0f, 7.0f, -1.0f, nullptr, nullptr, 0, 0, -1);
        tc_gemm<128, 256, 2, 4, 0, true, 1><<<dim3(1, 2, 16), 256, 0, s2>>>(
            xz + HO, tb + HO, ub + HO, CM, CM, CM, CM, MM, MM, MM,
            1.0f, 15.0f, -1.0f, nullptr, nullptr, 0, 0, -1);
        tc_gemm<128, 256, 2, 4, 0, true, 1><<<dim3(1, 2, 16), 256, 0, s2>>>(
            zc + HO, ub + HO, zn + HO, CM, CM, CM, CM, MM, MM, MM,
            0.25f, 13.0f, -1.0f, nullptr, nullptr, 0, 0, -1);
        bf16* tmp = zc; zc = zn; zn = tmp;
    }

    // --- s0: V projection (cols 1024..1535), a1, flash, conv ---
    tc_gemm<128, 256, 2, 4, 1, false, 1><<<dim3(2, CB * CN / 128, 1), 256>>>(
        xn, wq16, nullptr, CD, CD, CT3, 0, 0, 0, 0,
        1.0f, 0.0f, 1.0f, nullptr, nullptr, 4, 0, -1);
    tc_gemm<128, 256, 2, 4, 3, false, 1><<<dim3(1, CN / 128, CBH), 256>>>(
        q, klT, a1, CDH, CDH, CM, CM,
        NDH, (size_t)CDH * CM, (size_t)CN * CM, 1.0f, 0.0f, 1.0f,
        nullptr, nullptr, 0, 0, -1);
    flash_av<<<dim3(CM / 128, CBH), 256>>>();
    conv_res<<<(CBH * CN * CDH) / 1024, 256>>>(convw);
    cudaEventRecord(g_aux.evAV, 0);

    // --- zav halves on s1/s2 ---
    cudaStreamWaitEvent(s1, g_aux.evAV, 0);
    tc_gemm<64, 64, 4, 2, 0, false, 2><<<dim3(1, CM / 64, 16), 256, 0, s1>>>(
        zc, av, zav, CM, CM, CDH, CDH,
        MM, (size_t)CM * CDH, (size_t)CM * CDH, 1.0f, 0.0f, 1.0f,
        nullptr, nullptr, 0, 0, -1);
    cudaEventRecord(g_aux.evJ, s1);
    cudaStreamWaitEvent(s2, g_aux.evAV, 0);
    tc_gemm<64, 64, 4, 2, 0, false, 2><<<dim3(1, CM / 64, 16), 256, 0, s2>>>(
        zc + HO, av + AVH, zav + AVH, CM, CM, CDH, CDH,
        MM, (size_t)CM * CDH, (size_t)CM * CDH, 1.0f, 0.0f, 1.0f,
        nullptr, nullptr, 0, 0, -1);
    cudaEventRecord(g_aux.evJ2, s2);

    // --- pipelined tail ---
    cudaStreamWaitEvent(0, g_aux.evJ, 0);
    cudaStreamWaitEvent(0, g_aux.evJ2, 0);
    tc_gemm<128, 64, 4, 2, 4, false, 2><<<dim3(1, 16, CBH), 256>>>(
        a1, zav, outh, CM, CM, CDH, CDH,
        (size_t)CN * CM, (size_t)CM * CDH, NDH, 1.0f, 0.0f, 1.0f,
        nullptr, nullptr, 0, 0, -1);
    cudaStreamWaitEvent(s1, g_aux.evJ2, 0);
    tc_gemm<128, 64, 4, 2, 4, false, 2><<<dim3(1, 16, CBH), 256, 0, s1>>>(
        a1, zav, outh, CM, CM, CDH, CDH,
        (size_t)CN * CM, (size_t)CM * CDH, NDH, 1.0f, 0.0f, 1.0f,
        nullptr, nullptr, 0, 16, -1);
    cudaEventRecord(g_aux.evO2, s1);
    tc_gemm<128, 256, 2, 4, 2, false, 1><<<dim3(CD / 256, 64, 1), 256>>>(
        outh, wo16, out, CD, 0, CD, CD, 0, 0, 0, 1.0f, 0.0f, 1.0f,
        x, bout, 0, 0, 0);
    cudaStreamWaitEvent(0, g_aux.evO2, 0);
    tc_gemm<128, 256, 2, 4, 2, false, 1><<<dim3(CD / 256, 64, 1), 256>>>(
        outh, wo16, out, CD, 0, CD, CD, 0, 0, 0, 1.0f, 0.0f, 1.0f,
        x, bout, 0, 0, 1);
}

// round 17
// speedup vs baseline: 1.1650x; 1.1043x over previous
#include <cuda_runtime.h>
#include <cuda_bf16.h>
#include <math.h>
#include <stdint.h>

constexpr int CB  = 4;
constexpr int CN  = 4096;
constexpr int CD  = 512;
constexpr int CH  = 8;
constexpr int CDH = 64;
constexpr int CM  = 256;
constexpr int CL  = 16;
constexpr int CBH = CB * CH;    // 32
constexpr int CT3 = 3 * CD;     // 1536
constexpr float EPS = 1e-5f;

typedef __nv_bfloat16 bf16;
typedef __nv_bfloat162 bf162;

// ---------------------------------------------------------------------------
// Device scratch
// ---------------------------------------------------------------------------
__device__ __align__(16) bf16 g_xn  [(size_t)CB * CN * CD];
__device__ __align__(16) bf16 g_q   [(size_t)CBH * CN * CDH];
__device__ __align__(16) bf16 g_v   [(size_t)CBH * CN * CDH];
__device__ __align__(16) bf16 g_kT  [(size_t)CBH * CDH * CN];
__device__ __align__(16) bf16 g_ql  [(size_t)CBH * CM * CDH];
__device__ __align__(16) bf16 g_klT [(size_t)CBH * CDH * CM];
__device__ __align__(16) bf16 g_a1  [(size_t)CBH * CN * CM];
__device__ __align__(16) bf16 g_a2  [(size_t)CBH * CM * CM];
__device__ __align__(16) bf16 g_z   [(size_t)CBH * CM * CM];
__device__ __align__(16) bf16 g_z2  [(size_t)CBH * CM * CM];
__device__ __align__(16) bf16 g_xz  [(size_t)CBH * CM * CM];
__device__ __align__(16) bf16 g_av  [(size_t)CBH * CM * CDH];
__device__ __align__(16) bf16 g_zav [(size_t)CBH * CM * CDH];
__device__ __align__(16) bf16 g_outh[(size_t)CBH * CN * CDH];
__device__ __align__(16) bf16 g_wq16[(size_t)CD * CT3];
__device__ __align__(16) bf16 g_wo16[(size_t)CD * CD];
__device__ unsigned g_maxc, g_maxr;

// ---------------------------------------------------------------------------
// Fork/join resources (host-side only; created once at static init)
// ---------------------------------------------------------------------------
struct AuxStreams {
    cudaStream_t s1, s2;
    cudaEvent_t evF, evZ, evAV, evJ, evJ2, evO2;
    AuxStreams() {
        cudaStreamCreateWithFlags(&s1, cudaStreamNonBlocking);
        cudaStreamCreateWithFlags(&s2, cudaStreamNonBlocking);
        cudaEventCreateWithFlags(&evF,  cudaEventDisableTiming);
        cudaEventCreateWithFlags(&evZ,  cudaEventDisableTiming);
        cudaEventCreateWithFlags(&evAV, cudaEventDisableTiming);
        cudaEventCreateWithFlags(&evJ,  cudaEventDisableTiming);
        cudaEventCreateWithFlags(&evJ2, cudaEventDisableTiming);
        cudaEventCreateWithFlags(&evO2, cudaEventDisableTiming);
    }
};
static AuxStreams g_aux;

// ---------------------------------------------------------------------------
// helpers
// ---------------------------------------------------------------------------
__device__ __forceinline__ uint32_t pack2(float a, float b) {
    bf162 h = __floats2bfloat162_rn(a, b);
    return *reinterpret_cast<uint32_t*>(&h);
}
__device__ __forceinline__ float2 unpk(uint32_t u) {
    bf162 h = *reinterpret_cast<bf162*>(&u);
    return __bfloat1622float2(h);
}
__device__ __forceinline__ void mma16(float* c, const uint32_t* a,
                                      uint32_t b0, uint32_t b1) {
    asm volatile(
        "mma.sync.aligned.m16n8k16.row.col.f32.bf16.bf16.f32 "
        "{%0,%1,%2,%3},{%4,%5,%6,%7},{%8,%9},{%0,%1,%2,%3};"
        : "+f"(c[0]), "+f"(c[1]), "+f"(c[2]), "+f"(c[3])
        : "r"(a[0]), "r"(a[1]), "r"(a[2]), "r"(a[3]), "r"(b0), "r"(b1));
}
__device__ __forceinline__ void ldsm4(uint32_t* r, uint32_t addr) {
    asm volatile(
        "ldmatrix.sync.aligned.m8n8.x4.shared.b16 {%0,%1,%2,%3},[%4];"
        : "=r"(r[0]), "=r"(r[1]), "=r"(r[2]), "=r"(r[3]) : "r"(addr));
}
__device__ __forceinline__ void ldsm4t(uint32_t& r0, uint32_t& r1,
                                       uint32_t& r2, uint32_t& r3, uint32_t addr) {
    asm volatile(
        "ldmatrix.sync.aligned.m8n8.x4.trans.shared.b16 {%0,%1,%2,%3},[%4];"
        : "=r"(r0), "=r"(r1), "=r"(r2), "=r"(r3) : "r"(addr));
}

// ---------------------------------------------------------------------------
// bf16 tensor-core batched GEMM.  C = alpha * A @ (diagc*I + bsign*B)
// MODE 0: bf16 store  1: QKV scatter  2: final fp32 (+X+bias, gather A)
// MODE 3: fused row softmax (BN == row width)  4: bf16 accumulate
// xoff: column-block offset.  yoff: row-block offset.
// ysplit >= 0: row-block mapping by = (y/16)*32 + (y%16) + ysplit*16
// ---------------------------------------------------------------------------
template <int BM, int BN, int WGM, int WGN, int MODE, bool DIAG, int MINB>
__global__ __launch_bounds__(256, MINB)
void tc_gemm(const bf16* __restrict__ A, const bf16* __restrict__ B,
             void* __restrict__ Cp,
             int K, int lda, int ldb, int ldc,
             size_t sA, size_t sB, size_t sC,
             float alpha, float diagc, float bsign,
             const float* __restrict__ X, const float* __restrict__ bias,
             int xoff, int yoff, int ysplit) {
    constexpr int WROWS = BM / WGM;
    constexpr int WCOLS = BN / WGN;
    constexpr int MI    = WROWS / 16;
    constexpr int NFR   = WCOLS / 8;
    constexpr int TPRA  = 256 / BM;
    constexpr int KSPAN = 32 / TPRA;
    constexpr int NU4   = KSPAN / 8;
    constexpr int TPRB  = BN / 8;
    constexpr int RPPB  = 256 / TPRB;
    constexpr int BPASS = 32 / RPPB;
    constexpr int AP    = 40;
    constexpr int BPH   = BN + 8;

    __shared__ bf16 As[BM * AP];
    __shared__ bf16 Bs[32 * BPH];
    __shared__ float sred[(MODE == 3) ? 2 * BM * WGN : 2];

    const int t = threadIdx.x, warp = t >> 5, lane = t & 31;
    const int wm = warp / WGN, wn = warp % WGN;
    const int g = lane >> 2, tg = lane & 3;
    int by = blockIdx.y + yoff;
    if (ysplit >= 0)
        by = ((blockIdx.y >> 4) << 5) + (blockIdx.y & 15) + ysplit * 16;
    const int rowBase = by * BM;
    const int colBase = (blockIdx.x + xoff) * BN;
    const int arow = t % BM, akg = (t / BM) * KSPAN;
    const int brow = t / TPRB, bcol = (t % TPRB) * 8;

    const bf16* Ab = A + blockIdx.z * sA;
    const bf16* Bb = B + blockIdx.z * sB;

    const uint32_t asb = (uint32_t)__cvta_generic_to_shared(As);
    const uint32_t bsb = (uint32_t)__cvta_generic_to_shared(Bs);
    const uint32_t aoff = asb +
        ((((lane >> 3) & 1) * 8 + (lane & 7)) * AP + (lane >> 4) * 8) * 2;
    const uint32_t boff = bsb +
        ((((lane >> 3) & 1) * 8 + (lane & 7)) * BPH + wn * WCOLS + (lane >> 4) * 8) * 2;

    uint4 pa[NU4];
    uint4 pbb[BPASS];

    auto ldA = [&](int k0) {
        if (MODE == 2) {
            int r = rowBase + arow;
            int b_ = r >> 12, n = r & (CN - 1);
            int c = k0 + akg;
            int h_ = c >> 6, dh = c & 63;
            const bf16* p = Ab + ((((size_t)(b_ * CH + h_)) * CN + n) * CDH + dh);
#pragma unroll
            for (int i = 0; i < NU4; i++) pa[i] = *(const uint4*)(p + i * 8);
        } else {
            const bf16* p = Ab + (size_t)(rowBase + arow) * lda + k0 + akg;
#pragma unroll
            for (int i = 0; i < NU4; i++) pa[i] = *(const uint4*)(p + i * 8);
        }
    };
    auto ldB = [&](int k0) {
#pragma unroll
        for (int i = 0; i < BPASS; i++)
            pbb[i] = *(const uint4*)(Bb + (size_t)(k0 + brow + i * RPPB) * ldb +
                                     colBase + bcol);
    };
    auto stage = [&](int k0) {
#pragma unroll
        for (int i = 0; i < NU4; i++)
            *(uint4*)&As[arow * AP + akg + i * 8] = pa[i];
#pragma unroll
        for (int i = 0; i < BPASS; i++) {
            int r = brow + i * RPPB;
            uint4 u;
            if (DIAG) {
                float e[8];
                float2 f;
                f = unpk(pbb[i].x); e[0] = f.x; e[1] = f.y;
                f = unpk(pbb[i].y); e[2] = f.x; e[3] = f.y;
                f = unpk(pbb[i].z); e[4] = f.x; e[5] = f.y;
                f = unpk(pbb[i].w); e[6] = f.x; e[7] = f.y;
                int kr = k0 + r;
                int cb = colBase + bcol;
#pragma unroll
                for (int j = 0; j < 8; j++)
                    e[j] = bsign * e[j] + ((kr == cb + j) ? diagc : 0.0f);
                u.x = pack2(e[0], e[1]); u.y = pack2(e[2], e[3]);
                u.z = pack2(e[4], e[5]); u.w = pack2(e[6], e[7]);
            } else {
                u = pbb[i];
            }
            *(uint4*)&Bs[r * BPH + bcol] = u;
        }
    };

    float acc[MI][NFR][4] = {};

    ldA(0); ldB(0); stage(0);
    __syncthreads();
    for (int k0 = 0;; k0 += 32) {
        const int kn = k0 + 32;
        const bool more = kn < K;
        if (more) { ldA(kn); ldB(kn); }
#pragma unroll
        for (int ks = 0; ks < 2; ks++) {
            uint32_t af[MI][4];
#pragma unroll
            for (int mi = 0; mi < MI; mi++)
                ldsm4(af[mi], aoff + ((wm * WROWS + mi * 16) * AP + ks * 16) * 2);
            uint32_t bfr[NFR][2];
#pragma unroll
            for (int np = 0; np < NFR / 2; np++)
                ldsm4t(bfr[2 * np][0], bfr[2 * np][1],
                       bfr[2 * np + 1][0], bfr[2 * np + 1][1],
                       boff + (ks * 16 * BPH + np * 16) * 2);
#pragma unroll
            for (int ni = 0; ni < NFR; ni++)
#pragma unroll
                for (int mi = 0; mi < MI; mi++)
                    mma16(acc[mi][ni], af[mi], bfr[ni][0], bfr[ni][1]);
        }
        if (!more) break;
        __syncthreads();
        stage(kn);
        __syncthreads();
    }

    bf16*  Cb16 = (bf16*)Cp + blockIdx.z * sC;
    float* Cbf  = (float*)Cp + blockIdx.z * sC;

    if (MODE == 3) {
        float* smax = sred;
        float* ssum = sred + BM * WGN;
#pragma unroll
        for (int mi = 0; mi < MI; mi++)
#pragma unroll
            for (int h2 = 0; h2 < 2; h2++) {
                float m = -3.4e38f;
#pragma unroll
                for (int ni = 0; ni < NFR; ni++) {
                    m = fmaxf(m, acc[mi][ni][h2 * 2]);
                    m = fmaxf(m, acc[mi][ni][h2 * 2 + 1]);
                }
                m = fmaxf(m, __shfl_xor_sync(0xffffffffu, m, 1));
                m = fmaxf(m, __shfl_xor_sync(0xffffffffu, m, 2));
                int rl = wm * WROWS + mi * 16 + h2 * 8 + g;
                if (tg == 0) smax[rl * WGN + wn] = m;
            }
        __syncthreads();
#pragma unroll
        for (int mi = 0; mi < MI; mi++)
#pragma unroll
            for (int h2 = 0; h2 < 2; h2++) {
                int rl = wm * WROWS + mi * 16 + h2 * 8 + g;
                float tm = smax[rl * WGN];
#pragma unroll
                for (int w = 1; w < WGN; w++) tm = fmaxf(tm, smax[rl * WGN + w]);
                float s = 0.0f;
#pragma unroll
                for (int ni = 0; ni < NFR; ni++) {
                    float e0 = __expf(acc[mi][ni][h2 * 2]     - tm);
                    float e1 = __expf(acc[mi][ni][h2 * 2 + 1] - tm);
                    acc[mi][ni][h2 * 2]     = e0;
                    acc[mi][ni][h2 * 2 + 1] = e1;
                    s += e0 + e1;
                }
                s += __shfl_xor_sync(0xffffffffu, s, 1);
                s += __shfl_xor_sync(0xffffffffu, s, 2);
                if (tg == 0) ssum[rl * WGN + wn] = s;
            }
        __syncthreads();
#pragma unroll
        for (int mi = 0; mi < MI; mi++)
#pragma unroll
            for (int h2 = 0; h2 < 2; h2++) {
                int rl = wm * WROWS + mi * 16 + h2 * 8 + g;
                float s = 0.0f;
#pragma unroll
                for (int w = 0; w < WGN; w++) s += ssum[rl * WGN + w];
                float inv = 1.0f / s;
                int r = rowBase + rl;
#pragma unroll
                for (int ni = 0; ni < NFR; ni++) {
                    int c0 = colBase + wn * WCOLS + ni * 8 + 2 * tg;
                    *(uint32_t*)&Cb16[(size_t)r * ldc + c0] =
                        pack2(acc[mi][ni][h2 * 2] * inv,
                              acc[mi][ni][h2 * 2 + 1] * inv);
                }
            }
        return;
    }

#pragma unroll
    for (int mi = 0; mi < MI; mi++)
#pragma unroll
        for (int ni = 0; ni < NFR; ni++) {
            int r0 = rowBase + wm * WROWS + mi * 16 + g;
            int c0 = colBase + wn * WCOLS + ni * 8 + 2 * tg;
#pragma unroll
            for (int h2 = 0; h2 < 2; h2++) {
                int r = r0 + h2 * 8;
                float vx = alpha * acc[mi][ni][h2 * 2];
                float vy = alpha * acc[mi][ni][h2 * 2 + 1];
                if (MODE == 0) {
                    *(uint32_t*)&Cb16[(size_t)r * ldc + c0] = pack2(vx, vy);
                } else if (MODE == 4) {
                    uint32_t old = *(uint32_t*)&Cb16[(size_t)r * ldc + c0];
                    float2 f = unpk(old);
                    *(uint32_t*)&Cb16[(size_t)r * ldc + c0] =
                        pack2(vx + f.x, vy + f.y);
                } else if (MODE == 1) {
                    int b_ = r >> 12, n = r & (CN - 1);
                    int which = c0 >> 9, inner = c0 & 511;
                    int h_ = inner >> 6, dh = inner & 63;
                    size_t off = (((size_t)(b_ * CH + h_)) * CN + n) * CDH + dh;
                    if (which == 0) {
                        *(uint32_t*)&g_q[off] = pack2(vx * 0.125f, vy * 0.125f);
                    } else if (which == 1) {
                        size_t ot = (((size_t)(b_ * CH + h_)) * CDH + dh) * CN + n;
                        g_kT[ot]      = __float2bfloat16(vx);
                        g_kT[ot + CN] = __float2bfloat16(vy);
                    } else {
                        *(uint32_t*)&g_v[off] = pack2(vx, vy);
                    }
                } else {
                    size_t o = (size_t)r * CD + c0;
                    float2 xr = *(const float2*)&X[o];
                    float2 br = *(const float2*)&bias[c0];
                    *(float2*)&Cbf[o] = make_float2(vx + xr.x + br.x,
                                                    vy + xr.y + br.y);
                }
            }
        }
}

// ---------------------------------------------------------------------------
// Flash kernel: av = softmax_rows(ql @ k^T) @ v   (per bh, 128 m-rows/CTA)
// ---------------------------------------------------------------------------
__global__ __launch_bounds__(256, 1)
void flash_av() {
    constexpr int KP = 136;
    constexpr int VP = 72;
    __shared__ bf16 Ks[64 * KP];
    __shared__ bf16 Vs[128 * VP];

    const int t = threadIdx.x, warp = t >> 5, lane = t & 31;
    const int g = lane >> 2, tg = lane & 3;
    const int mb = blockIdx.x, bh = blockIdx.y;

    const bf16* qlb = g_ql + ((size_t)bh * CM + mb * 128) * CDH;
    const bf16* kTb = g_kT + (size_t)bh * CDH * CN;
    const bf16* vb  = g_v  + (size_t)bh * CN * CDH;

    const uint32_t ksb = (uint32_t)__cvta_generic_to_shared(Ks);
    const uint32_t vsb = (uint32_t)__cvta_generic_to_shared(Vs);
    const int rsel = ((lane >> 3) & 1) * 8 + (lane & 7);
    const int csel = (lane >> 4) * 8;

    for (int i = t; i < 1024; i += 256) {
        int row = i >> 3, cg = i & 7;
        *(uint4*)&Vs[row * VP + cg * 8] = *(const uint4*)&qlb[row * CDH + cg * 8];
    }
    __syncthreads();
    uint32_t qlA[4][4];
    {
        uint32_t base = vsb + ((warp * 16 + rsel) * VP + csel) * 2;
#pragma unroll
        for (int kb = 0; kb < 4; kb++) ldsm4(qlA[kb], base + kb * 16 * 2);
    }
    __syncthreads();

    float oacc[8][4] = {};
    float m0 = -1e30f, m1 = -1e30f, l0 = 0.0f, l1 = 0.0f;

    for (int ch = 0; ch < CN / 128; ch++) {
        for (int i = t; i < 1024; i += 256) {
            int row = i >> 4, cg = i & 15;
            *(uint4*)&Ks[row * KP + cg * 8] =
                *(const uint4*)&kTb[(size_t)row * CN + ch * 128 + cg * 8];
        }
        for (int i = t; i < 1024; i += 256) {
            int row = i >> 3, cg = i & 7;
            *(uint4*)&Vs[row * VP + cg * 8] =
                *(const uint4*)&vb[(size_t)(ch * 128 + row) * CDH + cg * 8];
        }
        __syncthreads();

        float sacc[16][4] = {};
#pragma unroll
        for (int ks = 0; ks < 4; ks++) {
            uint32_t brow = ksb + ((ks * 16 + rsel) * KP + csel) * 2;
#pragma unroll
            for (int np = 0; np < 8; np++) {
                uint32_t b0, b1, b2, b3;
                ldsm4t(b0, b1, b2, b3, brow + np * 16 * 2);
                mma16(sacc[2 * np],     qlA[ks], b0, b1);
                mma16(sacc[2 * np + 1], qlA[ks], b2, b3);
            }
        }

        float mx0 = m0, mx1 = m1;
#pragma unroll
        for (int ni = 0; ni < 16; ni++) {
            mx0 = fmaxf(mx0, fmaxf(sacc[ni][0], sacc[ni][1]));
            mx1 = fmaxf(mx1, fmaxf(sacc[ni][2], sacc[ni][3]));
        }
        mx0 = fmaxf(mx0, __shfl_xor_sync(0xffffffffu, mx0, 1));
        mx0 = fmaxf(mx0, __shfl_xor_sync(0xffffffffu, mx0, 2));
        mx1 = fmaxf(mx1, __shfl_xor_sync(0xffffffffu, mx1, 1));
        mx1 = fmaxf(mx1, __shfl_xor_sync(0xffffffffu, mx1, 2));
        float r0 = __expf(m0 - mx0), r1 = __expf(m1 - mx1);
        m0 = mx0; m1 = mx1;
        float s0 = 0.0f, s1 = 0.0f;
#pragma unroll
        for (int ni = 0; ni < 16; ni++) {
            sacc[ni][0] = __expf(sacc[ni][0] - m0);
            sacc[ni][1] = __expf(sacc[ni][1] - m0);
            sacc[ni][2] = __expf(sacc[ni][2] - m1);
            sacc[ni][3] = __expf(sacc[ni][3] - m1);
            s0 += sacc[ni][0] + sacc[ni][1];
            s1 += sacc[ni][2] + sacc[ni][3];
        }
        s0 += __shfl_xor_sync(0xffffffffu, s0, 1);
        s0 += __shfl_xor_sync(0xffffffffu, s0, 2);
        s1 += __shfl_xor_sync(0xffffffffu, s1, 1);
        s1 += __shfl_xor_sync(0xffffffffu, s1, 2);
        l0 = l0 * r0 + s0;
        l1 = l1 * r1 + s1;
#pragma unroll
        for (int f = 0; f < 8; f++) {
            oacc[f][0] *= r0; oacc[f][1] *= r0;
            oacc[f][2] *= r1; oacc[f][3] *= r1;
        }

#pragma unroll
        for (int kb = 0; kb < 8; kb++) {
            uint32_t pA[4];
            pA[0] = pack2(sacc[2 * kb][0],     sacc[2 * kb][1]);
            pA[1] = pack2(sacc[2 * kb][2],     sacc[2 * kb][3]);
            pA[2] = pack2(sacc[2 * kb + 1][0], sacc[2 * kb + 1][1]);
            pA[3] = pack2(sacc[2 * kb + 1][2], sacc[2 * kb + 1][3]);
            uint32_t vrow = vsb + ((kb * 16 + rsel) * VP + csel) * 2;
#pragma unroll
            for (int np = 0; np < 4; np++) {
                uint32_t b0, b1, b2, b3;
                ldsm4t(b0, b1, b2, b3, vrow + np * 16 * 2);
                mma16(oacc[2 * np],     pA, b0, b1);
                mma16(oacc[2 * np + 1], pA, b2, b3);
            }
        }
        __syncthreads();
    }

    float inv0 = 1.0f / l0, inv1 = 1.0f / l1;
    int row0 = mb * 128 + warp * 16 + g;
    bf16* avb = g_av + ((size_t)bh * CM) * CDH;
#pragma unroll
    for (int f = 0; f < 8; f++) {
        int c0 = f * 8 + 2 * tg;
        *(uint32_t*)&avb[(size_t)row0 * CDH + c0] =
            pack2(oacc[f][0] * inv0, oacc[f][1] * inv0);
        *(uint32_t*)&avb[(size_t)(row0 + 8) * CDH + c0] =
            pack2(oacc[f][2] * inv1, oacc[f][3] * inv1);
    }
}

// ---------------------------------------------------------------------------
__global__ void convert_w(const float* __restrict__ Wqkv,
                          const float* __restrict__ Wout) {
    int i = (blockIdx.x * 256 + threadIdx.x) * 4;
    const int n1 = CD * CT3;
    if (i < n1) {
        float4 v = *(const float4*)&Wqkv[i];
        uint2 o; o.x = pack2(v.x, v.y); o.y = pack2(v.z, v.w);
        *(uint2*)&g_wq16[i] = o;
    }
    if (i < CD * CD) {
        float4 v = *(const float4*)&Wout[i];
        uint2 o; o.x = pack2(v.x, v.y); o.y = pack2(v.z, v.w);
        *(uint2*)&g_wo16[i] = o;
    }
}

__global__ void ln_kernel(const float* __restrict__ x,
                          const float* __restrict__ gamma,
                          const float* __restrict__ beta) {
    int row = blockIdx.x;
    int t = threadIdx.x;
    const float4* xr = (const float4*)(x + (size_t)row * CD);
    float4 v = xr[t];
    float s  = v.x + v.y + v.z + v.w;
    float ss = v.x * v.x + v.y * v.y + v.z * v.z + v.w * v.w;
    __shared__ float shs[4], shss[4];
#pragma unroll
    for (int o = 16; o > 0; o >>= 1) {
        s  += __shfl_down_sync(0xffffffffu, s,  o);
        ss += __shfl_down_sync(0xffffffffu, ss, o);
    }
    int wid = t >> 5, lane = t & 31;
    if (!lane) { shs[wid] = s; shss[wid] = ss; }
    __syncthreads();
    s  = shs[0]  + shs[1]  + shs[2]  + shs[3];
    ss = shss[0] + shss[1] + shss[2] + shss[3];
    float mean = s * (1.0f / CD);
    float var  = ss * (1.0f / CD) - mean * mean;
    float inv  = rsqrtf(var + EPS);
    float4 gg = ((const float4*)gamma)[t];
    float4 bb = ((const float4*)beta)[t];
    uint2 o;
    o.x = pack2((v.x - mean) * inv * gg.x + bb.x, (v.y - mean) * inv * gg.y + bb.y);
    o.y = pack2((v.z - mean) * inv * gg.z + bb.z, (v.w - mean) * inv * gg.w + bb.w);
    *(uint2*)&g_xn[(size_t)row * CD + t * 4] = o;
}

__global__ void landmark_kernel() {
    int idx = blockIdx.x * 256 + threadIdx.x;
    int dh = idx & 63;
    int mi = (idx >> 6) & 255;
    int bh = idx >> 14;
    size_t qbase = ((size_t)bh * CN + mi * CL) * CDH + dh;
    float sq = 0.0f;
#pragma unroll
    for (int j = 0; j < CL; j++)
        sq += __bfloat162float(g_q[qbase + (size_t)j * CDH]);
    size_t kbase = ((size_t)bh * CDH + dh) * CN + mi * CL;
    float sk = 0.0f;
#pragma unroll
    for (int j = 0; j < CL; j++)
        sk += __bfloat162float(g_kT[kbase + j]);
    g_ql [((size_t)bh * CM + mi) * CDH + dh] = __float2bfloat16(sq * (1.0f / CL));
    g_klT[((size_t)bh * CDH + dh) * CM + mi] = __float2bfloat16(sk * (1.0f / CL));
}

__global__ void init_scalars() { g_maxc = 0u; g_maxr = 0u; }

// Coalesced absmax: col sums per-thread (coalesced); row sums warp-per-row.
__global__ void absmax_sums() {
    int bh = blockIdx.x;
    int t = threadIdx.x, warp = t >> 5, lane = t & 31;
    const bf16* a = g_a2 + (size_t)bh * CM * CM;
    float cs = 0.0f;
    for (int i = 0; i < CM; i++)
        cs += fabsf(__bfloat162float(a[(size_t)i * CM + t]));
    atomicMax(&g_maxr, __float_as_uint(cs));
    float rm = 0.0f;
    for (int r = warp; r < CM; r += 8) {
        float s = 0.0f;
        for (int c = lane; c < CM; c += 32)
            s += fabsf(__bfloat162float(a[(size_t)r * CM + c]));
#pragma unroll
        for (int o = 16; o > 0; o >>= 1) s += __shfl_xor_sync(0xffffffffu, s, o);
        rm = fmaxf(rm, s);
    }
    if (lane == 0) atomicMax(&g_maxc, __float_as_uint(rm));
}

// Coalesced transposed init: z[i][j] = a2[j][i] / denom via 32x32 smem tiles.
__global__ void zinit_kernel() {
    __shared__ float tile[32][33];
    int bh = blockIdx.z;
    int i0 = blockIdx.x * 32, j0 = blockIdx.y * 32;
    int tx = threadIdx.x, ty = threadIdx.y;   // 32 x 8
    size_t b = (size_t)bh << 16;
    float inv = 1.0f / (__uint_as_float(g_maxc) * __uint_as_float(g_maxr));
#pragma unroll
    for (int k = 0; k < 4; k++) {
        int row = ty + k * 8;
        tile[row][tx] = __bfloat162float(g_a2[b + (size_t)(j0 + row) * CM + i0 + tx]);
    }
    __syncthreads();
#pragma unroll
    for (int k = 0; k < 4; k++) {
        int row = ty + k * 8;
        g_z[b + (size_t)(i0 + row) * CM + j0 + tx] =
            __float2bfloat16(tile[tx][row] * inv);
    }
}

__global__ void conv_res(const float* __restrict__ w) {
    __shared__ float ws[33];
    int idx = blockIdx.x * 256 + threadIdx.x;
    int dh = idx & 63;
    int nq = (idx >> 6) & 1023;
    int bh = idx >> 16;
    int h_ = bh & 7;
    if (threadIdx.x < 33) ws[threadIdx.x] = w[h_ * 33 + threadIdx.x];
    __syncthreads();
    int n0 = nq * 4;
    size_t base = ((size_t)bh * CN) * CDH + dh;
    float vv[36];
#pragma unroll
    for (int j = 0; j < 36; j++) {
        int nn = n0 - 16 + j;
        vv[j] = (nn >= 0 && nn < CN)
                    ? __bfloat162float(g_v[base + (size_t)nn * CDH]) : 0.0f;
    }
#pragma unroll
    for (int i = 0; i < 4; i++) {
        float s = 0.0f;
#pragma unroll
        for (int k2 = 0; k2 < 33; k2++) s += ws[k2] * vv[k2 + i];
        g_outh[base + (size_t)(n0 + i) * CDH] = __float2bfloat16(s);
    }
}

// ---------------------------------------------------------------------------
// Launch (round-16 schedule; quadratic Newton-Schulz pinv: 8 iters x 2 GEMMs)
// ---------------------------------------------------------------------------
extern "C" void kernel_launch(void* const* d_in, const int* in_sizes, int n_in,
                              void* d_out, int out_size) {
    const float* x     = (const float*)d_in[0];
    const float* gamma = (const float*)d_in[1];
    const float* beta  = (const float*)d_in[2];
    const float* Wqkv  = (const float*)d_in[3];
    const float* Wout  = (const float*)d_in[4];
    const float* bout  = (const float*)d_in[5];
    const float* convw = (const float*)d_in[6];
    float* out = (float*)d_out;

    bf16 *xn, *q, *v, *kT, *ql, *klT, *a1, *a2;
    bf16 *z, *z2, *xz, *av, *zav, *outh, *wq16, *wo16;
    void* p;
    cudaGetSymbolAddress(&p, g_xn);   xn   = (bf16*)p;
    cudaGetSymbolAddress(&p, g_q);    q    = (bf16*)p;
    cudaGetSymbolAddress(&p, g_v);    v    = (bf16*)p;
    cudaGetSymbolAddress(&p, g_kT);   kT   = (bf16*)p;
    cudaGetSymbolAddress(&p, g_ql);   ql   = (bf16*)p;
    cudaGetSymbolAddress(&p, g_klT);  klT  = (bf16*)p;
    cudaGetSymbolAddress(&p, g_a1);   a1   = (bf16*)p;
    cudaGetSymbolAddress(&p, g_a2);   a2   = (bf16*)p;
    cudaGetSymbolAddress(&p, g_z);    z    = (bf16*)p;
    cudaGetSymbolAddress(&p, g_z2);   z2   = (bf16*)p;
    cudaGetSymbolAddress(&p, g_xz);   xz   = (bf16*)p;
    cudaGetSymbolAddress(&p, g_av);   av   = (bf16*)p;
    cudaGetSymbolAddress(&p, g_zav);  zav  = (bf16*)p;
    cudaGetSymbolAddress(&p, g_outh); outh = (bf16*)p;
    cudaGetSymbolAddress(&p, g_wq16); wq16 = (bf16*)p;
    cudaGetSymbolAddress(&p, g_wo16); wo16 = (bf16*)p;

    const size_t MM  = (size_t)CM * CM;
    const size_t NDH = (size_t)CN * CDH;
    const size_t AVH = (size_t)16 * CM * CDH;
    cudaStream_t s1 = g_aux.s1, s2 = g_aux.s2;
    const size_t HO = (size_t)16 * MM;

    // --- s0 prefix: LN, weights, QK projection (cols 0..1023), landmark ---
    ln_kernel<<<CB * CN, 128>>>(x, gamma, beta);
    convert_w<<<(CD * CT3) / 1024, 256>>>(Wqkv, Wout);
    tc_gemm<128, 256, 2, 4, 1, false, 1><<<dim3(4, CB * CN / 128, 1), 256>>>(
        xn, wq16, nullptr, CD, CD, CT3, 0, 0, 0, 0,
        1.0f, 0.0f, 1.0f, nullptr, nullptr, 0, 0, -1);
    landmark_kernel<<<(CBH * CM * CDH) / 256, 256>>>();
    cudaEventRecord(g_aux.evF, 0);

    // --- s1: a2 + pinv init + half-chain bh 0-15 (critical path) ---
    cudaStreamWaitEvent(s1, g_aux.evF, 0);
    tc_gemm<128, 256, 2, 4, 3, false, 1><<<dim3(1, CM / 128, CBH), 256, 0, s1>>>(
        ql, klT, a2, CDH, CDH, CM, CM,
        (size_t)CM * CDH, (size_t)CDH * CM, MM, 1.0f, 0.0f, 1.0f,
        nullptr, nullptr, 0, 0, -1);
    init_scalars<<<1, 1, 0, s1>>>();
    absmax_sums<<<CBH, 256, 0, s1>>>();
    zinit_kernel<<<dim3(CM / 32, CM / 32, CBH), dim3(32, 8), 0, s1>>>();
    cudaEventRecord(g_aux.evZ, s1);
    cudaStreamWaitEvent(s2, g_aux.evZ, 0);

    // quadratic Newton-Schulz: z' = z(2I - a2 z), 8 iterations
    bf16* zc = z;
    bf16* zn = z2;
    for (int it = 0; it < 8; it++) {
        tc_gemm<128, 256, 2, 4, 0, false, 1><<<dim3(1, 2, 16), 256, 0, s1>>>(
            a2, zc, xz, CM, CM, CM, CM, MM, MM, MM, 1.0f, 0.0f, 1.0f,
            nullptr, nullptr, 0, 0, -1);
        tc_gemm<128, 256, 2, 4, 0, true, 1><<<dim3(1, 2, 16), 256, 0, s1>>>(
            zc, xz, zn, CM, CM, CM, CM, MM, MM, MM, 1.0f, 2.0f, -1.0f,
            nullptr, nullptr, 0, 0, -1);
        tc_gemm<128, 256, 2, 4, 0, false, 1><<<dim3(1, 2, 16), 256, 0, s2>>>(
            a2 + HO, zc + HO, xz + HO, CM, CM, CM, CM, MM, MM, MM,
            1.0f, 0.0f, 1.0f, nullptr, nullptr, 0, 0, -1);
        tc_gemm<128, 256, 2, 4, 0, true, 1><<<dim3(1, 2, 16), 256, 0, s2>>>(
            zc + HO, xz + HO, zn + HO, CM, CM, CM, CM, MM, MM, MM,
            1.0f, 2.0f, -1.0f, nullptr, nullptr, 0, 0, -1);
        bf16* tmp = zc; zc = zn; zn = tmp;
    }

    // --- s0: V projection (cols 1024..1535), a1, flash, conv ---
    tc_gemm<128, 256, 2, 4, 1, false, 1><<<dim3(2, CB * CN / 128, 1), 256>>>(
        xn, wq16, nullptr, CD, CD, CT3, 0, 0, 0, 0,
        1.0f, 0.0f, 1.0f, nullptr, nullptr, 4, 0, -1);
    tc_gemm<128, 256, 2, 4, 3, false, 1><<<dim3(1, CN / 128, CBH), 256>>>(
        q, klT, a1, CDH, CDH, CM, CM,
        NDH, (size_t)CDH * CM, (size_t)CN * CM, 1.0f, 0.0f, 1.0f,
        nullptr, nullptr, 0, 0, -1);
    flash_av<<<dim3(CM / 128, CBH), 256>>>();
    conv_res<<<(CBH * CN * CDH) / 1024, 256>>>(convw);
    cudaEventRecord(g_aux.evAV, 0);

    // --- zav halves on s1/s2 ---
    cudaStreamWaitEvent(s1, g_aux.evAV, 0);
    tc_gemm<64, 64, 4, 2, 0, false, 2><<<dim3(1, CM / 64, 16), 256, 0, s1>>>(
        zc, av, zav, CM, CM, CDH, CDH,
        MM, (size_t)CM * CDH, (size_t)CM * CDH, 1.0f, 0.0f, 1.0f,
        nullptr, nullptr, 0, 0, -1);
    cudaEventRecord(g_aux.evJ, s1);
    cudaStreamWaitEvent(s2, g_aux.evAV, 0);
    tc_gemm<64, 64, 4, 2, 0, false, 2><<<dim3(1, CM / 64, 16), 256, 0, s2>>>(
        zc + HO, av + AVH, zav + AVH, CM, CM, CDH, CDH,
        MM, (size_t)CM * CDH, (size_t)CM * CDH, 1.0f, 0.0f, 1.0f,
        nullptr, nullptr, 0, 0, -1);
    cudaEventRecord(g_aux.evJ2, s2);

    // --- pipelined tail ---
    cudaStreamWaitEvent(0, g_aux.evJ, 0);
    cudaStreamWaitEvent(0, g_aux.evJ2, 0);
    tc_gemm<128, 64, 4, 2, 4, false, 2><<<dim3(1, 16, CBH), 256>>>(
        a1, zav, outh, CM, CM, CDH, CDH,
        (size_t)CN * CM, (size_t)CM * CDH, NDH, 1.0f, 0.0f, 1.0f,
        nullptr, nullptr, 0, 0, -1);
    cudaStreamWaitEvent(s1, g_aux.evJ2, 0);
    tc_gemm<128, 64, 4, 2, 4, false, 2><<<dim3(1, 16, CBH), 256, 0, s1>>>(
        a1, zav, outh, CM, CM, CDH, CDH,
        (size_t)CN * CM, (size_t)CM * CDH, NDH, 1.0f, 0.0f, 1.0f,
        nullptr, nullptr, 0, 16, -1);
    cudaEventRecord(g_aux.evO2, s1);
    tc_gemm<128, 256, 2, 4, 2, false, 1><<<dim3(CD / 256, 64, 1), 256>>>(
        outh, wo16, out, CD, 0, CD, CD, 0, 0, 0, 1.0f, 0.0f, 1.0f,
        x, bout, 0, 0, 0);
    cudaStreamWaitEvent(0, g_aux.evO2, 0);
    tc_gemm<128, 256, 2, 4, 2, false, 1><<<dim3(CD / 256, 64, 1), 256>>>(
        outh, wo16, out, CD, 0, CD, CD, 0, 0, 0, 1.0f, 0.0f, 1.0f,
        x, bout, 0, 0, 1);
}